// round 13
// baseline (speedup 1.0000x reference)
#include <cuda_runtime.h>
#include <cuda_fp16.h>
#include <cstdint>

#define MDIM 12288
#define CIN 8
#define NPAIR 4
#define COUT 16
#define KTAP 5

#define RPW 7                    // rows per consumer warp
#define NWC 4                    // consumer warps
#define RPB (RPW * NWC)          // 28 rows per CTA
#define NCTHR (NWC * 32)         // 128 consumer threads
#define NTHR (NCTHR + 32)        // +1 producer warp = 160
#define GRID 439                 // ceil(12288/28)

#define SCOLS 128                // columns per ring stage
#define NS 4                     // ring depth
#define NSTG (MDIM / SCOLS)      // 96

// fp32 step (step 1)
#define STAGE_L32 (RPB * SCOLS * 4)      // 14336 B
#define STAGE_P   (SCOLS * CIN * 4)      // 4096 B
#define STAGE_B32 (STAGE_L32 + STAGE_P)  // 18432 B
#define SMEM32 (128 + NS * STAGE_B32)    // 73856 -> 3 CTAs/SM

// fp16 step (steps 2-4)
#define STAGE_L16 (RPB * SCOLS * 2)      // 7168 B
#define STAGE_B16 (STAGE_L16 + STAGE_P)  // 11264 B
#define SMEM16 (128 + NS * STAGE_B16)    // 45184 -> 3 CTAs/SM

#define SM_FULL  0
#define SM_EMPTY 64
#define SM_RING  128

#define SWZ(b) ((b) ^ (((b) >> 3) & 0x70))

// Panels column-major [M][CIN]; fp16 shadow of L written by step 1.
__device__ __align__(16) float g_pan[KTAP - 1][MDIM * CIN];
__device__ __align__(16) float g_xT[MDIM * CIN];
__device__ __align__(16) __half g_L16[(size_t)MDIM * MDIM];

// ---------- helpers ----------
__device__ __forceinline__ uint32_t smem_u32(const void* p) {
    uint32_t a;
    asm("{ .reg .u64 t; cvta.to.shared.u64 t, %1; cvt.u32.u64 %0, t; }" : "=r"(a) : "l"(p));
    return a;
}
__device__ __forceinline__ unsigned long long pack2(float lo, float hi) {
    unsigned long long r;
    asm("mov.b64 %0, {%1, %2};" : "=l"(r) : "f"(lo), "f"(hi));
    return r;
}
__device__ __forceinline__ void unpack2(unsigned long long v, float& lo, float& hi) {
    asm("mov.b64 {%0, %1}, %2;" : "=f"(lo), "=f"(hi) : "l"(v));
}
__device__ __forceinline__ void fma2(unsigned long long& acc,
                                     unsigned long long a, unsigned long long b) {
    asm("fma.rn.f32x2 %0, %1, %2, %0;" : "+l"(acc) : "l"(a), "l"(b));
}
__device__ __forceinline__ void cp16(uint32_t dst, const void* src) {
    asm volatile("cp.async.cg.shared.global [%0], [%1], 16;" :: "r"(dst), "l"(src) : "memory");
}
__device__ __forceinline__ void cp_commit() {
    asm volatile("cp.async.commit_group;" ::: "memory");
}
template <int N>
__device__ __forceinline__ void cp_wait() {
    asm volatile("cp.async.wait_group %0;" :: "n"(N) : "memory");
}
__device__ __forceinline__ void mbar_init(uint32_t a, uint32_t cnt) {
    asm volatile("mbarrier.init.shared.b64 [%0], %1;" :: "r"(a), "r"(cnt) : "memory");
}
__device__ __forceinline__ void mbar_arrive(uint32_t a) {
    asm volatile("mbarrier.arrive.release.cta.shared::cta.b64 _, [%0];" :: "r"(a) : "memory");
}
__device__ __forceinline__ void mbar_wait_acq(uint32_t a, uint32_t ph) {
    asm volatile(
        "{\n\t.reg .pred P;\n\t"
        "WL%=:\n\t"
        "mbarrier.try_wait.parity.acquire.cta.shared::cta.b64 P, [%0], %1, 0x989680;\n\t"
        "@P bra.uni WD%=;\n\t"
        "bra.uni WL%=;\n\t"
        "WD%=:\n\t}"
        :: "r"(a), "r"(ph) : "memory");
}

// xT[m*8 + i] = x[i*M + m]
__global__ __launch_bounds__(256)
void transpose_kernel(const float* __restrict__ x, float* __restrict__ xT) {
    const int m = blockIdx.x * blockDim.x + threadIdx.x;
    if (m >= MDIM) return;
    float v[CIN];
#pragma unroll
    for (int i = 0; i < CIN; ++i) v[i] = x[(size_t)i * MDIM + m];
    float4* dst = reinterpret_cast<float4*>(xT + (size_t)m * CIN);
    dst[0] = make_float4(v[0], v[1], v[2], v[3]);
    dst[1] = make_float4(v[4], v[5], v[6], v[7]);
}

// ===================== step 1: fp32 L, also emits fp16 shadow =====================
__global__ __launch_bounds__(NTHR, 3)
void step32_kernel(const float* __restrict__ L,
                   const float* __restrict__ cur,
                   float* __restrict__ nxt,
                   __half* __restrict__ L16out) {
    extern __shared__ __align__(128) unsigned char dsm[];
    const uint32_t smb = smem_u32(dsm);
    const int tid  = threadIdx.x;
    const int lane = tid & 31;
    const int w    = tid >> 5;
    const int m0   = blockIdx.x * RPB;

    if (tid == 0) {
#pragma unroll
        for (int s = 0; s < NS; ++s) {
            mbar_init(smb + SM_FULL  + 8 * s, 32);
            mbar_init(smb + SM_EMPTY + 8 * s, NWC);
        }
    }
    __syncthreads();

    if (w == NWC) {
        const unsigned char* curb = reinterpret_cast<const unsigned char*>(cur);
        int eph = 1;
        for (int u = 0; u < NSTG; ++u) {
            const int slot = u & (NS - 1);
            mbar_wait_acq(smb + SM_EMPTY + 8 * slot, (uint32_t)eph);
            const uint32_t dst0 = smb + SM_RING + slot * STAGE_B32;
            const int jb = u * SCOLS;                 // forward only
#pragma unroll
            for (int r = 0; r < RPB; ++r) {
                int mr = m0 + r; if (mr > MDIM - 1) mr = MDIM - 1;
                cp16(dst0 + r * (SCOLS * 4) + lane * 16,
                     L + (size_t)mr * MDIM + jb + lane * 4);
            }
#pragma unroll
            for (int q = 0; q < 8; ++q) {
                const uint32_t off = (uint32_t)(lane * 16 + q * 512);
                cp16(dst0 + STAGE_L32 + SWZ(off),
                     curb + (size_t)jb * 32 + off);
            }
            cp_commit();
            if (u >= 2) { cp_wait<2>(); mbar_arrive(smb + SM_FULL + 8 * ((u - 2) & (NS - 1))); }
            if (slot == NS - 1) eph ^= 1;
        }
        cp_wait<1>(); mbar_arrive(smb + SM_FULL + 8 * ((NSTG - 2) & (NS - 1)));
        cp_wait<0>(); mbar_arrive(smb + SM_FULL + 8 * ((NSTG - 1) & (NS - 1)));
        return;
    }

    const int r0 = w * RPW;
    unsigned long long acc[RPW][NPAIR];
#pragma unroll
    for (int r = 0; r < RPW; ++r)
#pragma unroll
        for (int p = 0; p < NPAIR; ++p) acc[r][p] = 0ull;

    int fph = 0;
    for (int u = 0; u < NSTG; ++u) {
        const int slot = u & (NS - 1);
        mbar_wait_acq(smb + SM_FULL + 8 * slot, (uint32_t)fph);

        const unsigned char* lb = dsm + SM_RING + slot * STAGE_B32;
        float4 a[RPW];
#pragma unroll
        for (int r = 0; r < RPW; ++r)
            a[r] = *reinterpret_cast<const float4*>(
                       lb + (r0 + r) * (SCOLS * 4) + lane * 16);

        // emit fp16 shadow of L (this CTA's rows, this stage's columns)
        const int jc = u * SCOLS + 4 * lane;          // global column of a[].x
#pragma unroll
        for (int r = 0; r < RPW; ++r) {
            const int m = m0 + r0 + r;
            if (m < MDIM) {
                __half2 h01 = __floats2half2_rn(a[r].x, a[r].y);
                __half2 h23 = __floats2half2_rn(a[r].z, a[r].w);
                uint2 pkd;
                pkd.x = *reinterpret_cast<uint32_t*>(&h01);
                pkd.y = *reinterpret_cast<uint32_t*>(&h23);
                *reinterpret_cast<uint2*>(L16out + (size_t)m * MDIM + jc) = pkd;
            }
        }

        const unsigned char* pbp = lb + STAGE_L32;
#pragma unroll
        for (int jj = 0; jj < 4; ++jj) {
            const int jl = 4 * lane + jj;
            ulonglong2 q0 = *reinterpret_cast<const ulonglong2*>(pbp + SWZ(jl * 32));
            ulonglong2 q1 = *reinterpret_cast<const ulonglong2*>(pbp + SWZ(jl * 32 + 16));
#pragma unroll
            for (int r = 0; r < RPW; ++r) {
                float av = (jj == 0) ? a[r].x : (jj == 1) ? a[r].y
                         : (jj == 2) ? a[r].z : a[r].w;
                unsigned long long aa = pack2(av, av);
                fma2(acc[r][0], aa, q0.x);
                fma2(acc[r][1], aa, q0.y);
                fma2(acc[r][2], aa, q1.x);
                fma2(acc[r][3], aa, q1.y);
            }
        }

        if (lane == 0) mbar_arrive(smb + SM_EMPTY + 8 * slot);
        if (slot == NS - 1) fph ^= 1;
    }

#pragma unroll
    for (int r = 0; r < RPW; ++r) {
        const int m = m0 + r0 + r;
        float ov[CIN];
#pragma unroll
        for (int p = 0; p < NPAIR; ++p) {
            float v0, v1;
            unpack2(acc[r][p], v0, v1);
#pragma unroll
            for (int d = 16; d > 0; d >>= 1) {
                v0 += __shfl_down_sync(0xffffffffu, v0, d);
                v1 += __shfl_down_sync(0xffffffffu, v1, d);
            }
            ov[2 * p] = v0; ov[2 * p + 1] = v1;
        }
        if (lane == 0 && m < MDIM) {
            float4* dst = reinterpret_cast<float4*>(nxt + (size_t)m * CIN);
            dst[0] = make_float4(ov[0], ov[1], ov[2], ov[3]);
            dst[1] = make_float4(ov[4], ov[5], ov[6], ov[7]);
        }
    }
}

// ===================== steps 2-4: fp16 L shadow =====================
__global__ __launch_bounds__(NTHR, 3)
void step16_kernel(const __half* __restrict__ Lh,
                   const float* __restrict__ cur,
                   float* __restrict__ nxt,
                   int dir) {
    extern __shared__ __align__(128) unsigned char dsm[];
    const uint32_t smb = smem_u32(dsm);
    const int tid  = threadIdx.x;
    const int lane = tid & 31;
    const int w    = tid >> 5;
    const int m0   = blockIdx.x * RPB;

    if (tid == 0) {
#pragma unroll
        for (int s = 0; s < NS; ++s) {
            mbar_init(smb + SM_FULL  + 8 * s, 32);
            mbar_init(smb + SM_EMPTY + 8 * s, NWC);
        }
    }
    __syncthreads();

    if (w == NWC) {
        const unsigned char* curb = reinterpret_cast<const unsigned char*>(cur);
        int eph = 1;
        for (int u = 0; u < NSTG; ++u) {
            const int t    = dir ? (NSTG - 1 - u) : u;
            const int slot = u & (NS - 1);
            mbar_wait_acq(smb + SM_EMPTY + 8 * slot, (uint32_t)eph);
            const uint32_t dst0 = smb + SM_RING + slot * STAGE_B16;
            const int jb = t * SCOLS;
            // L16 chunk: 28 rows x 256 B; two rows per iteration (16 lanes each)
#pragma unroll
            for (int rr = 0; rr < RPB / 2; ++rr) {
                int row = rr * 2 + (lane >> 4);
                int mr = m0 + row; if (mr > MDIM - 1) mr = MDIM - 1;
                cp16(dst0 + row * (SCOLS * 2) + (lane & 15) * 16,
                     reinterpret_cast<const unsigned char*>(
                         Lh + (size_t)mr * MDIM + jb) + (lane & 15) * 16);
            }
#pragma unroll
            for (int q = 0; q < 8; ++q) {
                const uint32_t off = (uint32_t)(lane * 16 + q * 512);
                cp16(dst0 + STAGE_L16 + SWZ(off),
                     curb + (size_t)jb * 32 + off);
            }
            cp_commit();
            if (u >= 2) { cp_wait<2>(); mbar_arrive(smb + SM_FULL + 8 * ((u - 2) & (NS - 1))); }
            if (slot == NS - 1) eph ^= 1;
        }
        cp_wait<1>(); mbar_arrive(smb + SM_FULL + 8 * ((NSTG - 2) & (NS - 1)));
        cp_wait<0>(); mbar_arrive(smb + SM_FULL + 8 * ((NSTG - 1) & (NS - 1)));
        return;
    }

    const int r0 = w * RPW;
    unsigned long long acc[RPW][NPAIR];
#pragma unroll
    for (int r = 0; r < RPW; ++r)
#pragma unroll
        for (int p = 0; p < NPAIR; ++p) acc[r][p] = 0ull;

    int fph = 0;
    for (int u = 0; u < NSTG; ++u) {
        const int slot = u & (NS - 1);
        mbar_wait_acq(smb + SM_FULL + 8 * slot, (uint32_t)fph);

        const unsigned char* lb = dsm + SM_RING + slot * STAGE_B16;
        float4 a[RPW];
#pragma unroll
        for (int r = 0; r < RPW; ++r) {
            uint2 raw = *reinterpret_cast<const uint2*>(
                            lb + (r0 + r) * (SCOLS * 2) + lane * 8);
            __half2 h01 = *reinterpret_cast<__half2*>(&raw.x);
            __half2 h23 = *reinterpret_cast<__half2*>(&raw.y);
            float2 f01 = __half22float2(h01);
            float2 f23 = __half22float2(h23);
            a[r] = make_float4(f01.x, f01.y, f23.x, f23.y);
        }

        const unsigned char* pbp = lb + STAGE_L16;
#pragma unroll
        for (int jj = 0; jj < 4; ++jj) {
            const int jl = 4 * lane + jj;
            ulonglong2 q0 = *reinterpret_cast<const ulonglong2*>(pbp + SWZ(jl * 32));
            ulonglong2 q1 = *reinterpret_cast<const ulonglong2*>(pbp + SWZ(jl * 32 + 16));
#pragma unroll
            for (int r = 0; r < RPW; ++r) {
                float av = (jj == 0) ? a[r].x : (jj == 1) ? a[r].y
                         : (jj == 2) ? a[r].z : a[r].w;
                unsigned long long aa = pack2(av, av);
                fma2(acc[r][0], aa, q0.x);
                fma2(acc[r][1], aa, q0.y);
                fma2(acc[r][2], aa, q1.x);
                fma2(acc[r][3], aa, q1.y);
            }
        }

        if (lane == 0) mbar_arrive(smb + SM_EMPTY + 8 * slot);
        if (slot == NS - 1) fph ^= 1;
    }

#pragma unroll
    for (int r = 0; r < RPW; ++r) {
        const int m = m0 + r0 + r;
        float ov[CIN];
#pragma unroll
        for (int p = 0; p < NPAIR; ++p) {
            float v0, v1;
            unpack2(acc[r][p], v0, v1);
#pragma unroll
            for (int d = 16; d > 0; d >>= 1) {
                v0 += __shfl_down_sync(0xffffffffu, v0, d);
                v1 += __shfl_down_sync(0xffffffffu, v1, d);
            }
            ov[2 * p] = v0; ov[2 * p + 1] = v1;
        }
        if (lane == 0 && m < MDIM) {
            float4* dst = reinterpret_cast<float4*>(nxt + (size_t)m * CIN);
            dst[0] = make_float4(ov[0], ov[1], ov[2], ov[3]);
            dst[1] = make_float4(ov[4], ov[5], ov[6], ov[7]);
        }
    }
}

// y[o][m] = bias[o] + sum_{i,k} theta[o][i][k] * P[k][m][i]
__global__ __launch_bounds__(256)
void mix_kernel(const float* __restrict__ x,
                const float* __restrict__ theta,
                const float* __restrict__ bias,
                float* __restrict__ out) {
    __shared__ float th[COUT * CIN * KTAP];
    __shared__ float bs[COUT];
    const int tid = threadIdx.x;
    for (int idx = tid; idx < COUT * CIN * KTAP; idx += blockDim.x)
        th[idx] = theta[idx];
    if (tid < COUT) bs[tid] = bias[tid];
    __syncthreads();

    const int m = blockIdx.x * blockDim.x + tid;
    if (m >= MDIM) return;

    float p[KTAP][CIN];
#pragma unroll
    for (int i = 0; i < CIN; ++i) p[0][i] = x[(size_t)i * MDIM + m];
#pragma unroll
    for (int k = 1; k < KTAP; ++k) {
        const float4* src = reinterpret_cast<const float4*>(
                                &g_pan[k - 1][(size_t)m * CIN]);
        float4 lo = src[0], hi = src[1];
        p[k][0] = lo.x; p[k][1] = lo.y; p[k][2] = lo.z; p[k][3] = lo.w;
        p[k][4] = hi.x; p[k][5] = hi.y; p[k][6] = hi.z; p[k][7] = hi.w;
    }

#pragma unroll
    for (int o = 0; o < COUT; ++o) {
        float s = bs[o];
#pragma unroll
        for (int i = 0; i < CIN; ++i)
#pragma unroll
            for (int k = 0; k < KTAP; ++k)
                s += th[(o * CIN + i) * KTAP + k] * p[k][i];
        out[(size_t)o * MDIM + m] = s;
    }
}

extern "C" void kernel_launch(void* const* d_in, const int* in_sizes, int n_in,
                              void* d_out, int out_size) {
    const float* L     = (const float*)d_in[0];
    const float* x     = (const float*)d_in[1];
    const float* theta = (const float*)d_in[2];
    const float* bias  = (const float*)d_in[3];
    float* out = (float*)d_out;

    cudaFuncSetAttribute(step32_kernel,
                         cudaFuncAttributeMaxDynamicSharedMemorySize, SMEM32);
    cudaFuncSetAttribute(step16_kernel,
                         cudaFuncAttributeMaxDynamicSharedMemorySize, SMEM16);

    float* pan = nullptr;
    cudaGetSymbolAddress((void**)&pan, g_pan);
    float* xT = nullptr;
    cudaGetSymbolAddress((void**)&xT, g_xT);
    __half* L16 = nullptr;
    cudaGetSymbolAddress((void**)&L16, g_L16);

    const size_t PSZ = (size_t)MDIM * CIN;

    transpose_kernel<<<(MDIM + 255) / 256, 256>>>(x, xT);
    // Step 1: fp32 L read (forward), emits fp16 shadow of L.
    step32_kernel<<<GRID, NTHR, SMEM32>>>(L, xT, pan + 0 * PSZ, L16);
    // Steps 2-4: fp16 shadow, serpentine order (step 2 reversed hits the
    // L2 write-residue of step 1's shadow emission).
    step16_kernel<<<GRID, NTHR, SMEM16>>>(L16, pan + 0 * PSZ, pan + 1 * PSZ, 1);
    step16_kernel<<<GRID, NTHR, SMEM16>>>(L16, pan + 1 * PSZ, pan + 2 * PSZ, 0);
    step16_kernel<<<GRID, NTHR, SMEM16>>>(L16, pan + 2 * PSZ, pan + 3 * PSZ, 1);

    mix_kernel<<<(MDIM + 255) / 256, 256>>>(x, theta, bias, out);
}

// round 14
// speedup vs baseline: 1.2512x; 1.2512x over previous
#include <cuda_runtime.h>
#include <cuda_fp16.h>
#include <cstdint>

#define MDIM 12288
#define CIN 8
#define NPAIR 4
#define COUT 16
#define KTAP 5

// ---------- step32 (step 1) geometry: identical to R11 winner ----------
#define RPW 7
#define NWC 4
#define RPB (RPW * NWC)          // 28
#define NCTHR (NWC * 32)
#define NTHR (NCTHR + 32)        // 160
#define GRID32 439

#define SCOLS 128
#define NS 4
#define NSTG (MDIM / SCOLS)      // 96
#define STAGE_L32 (RPB * SCOLS * 4)      // 14336
#define STAGE_P32 (SCOLS * CIN * 4)      // 4096
#define STAGE_B32 (STAGE_L32 + STAGE_P32)
#define SMEM32 (128 + NS * STAGE_B32)    // 73856

// ---------- step16 MMA geometry ----------
#define MROWS 64                 // rows per CTA (4 warps x 16)
#define GRID16 (MDIM / MROWS)    // 192
#define M_STAGE_L (MROWS * SCOLS * 2)    // 16384 (fp16, 256B/row, swizzled)
#define M_STAGE_P (SCOLS * CIN * 2)      // 2048  (fp16 panel, linear)
#define M_STAGE_B (M_STAGE_L + M_STAGE_P)  // 18432
#define SMEM16 (128 + NS * M_STAGE_B)    // 73856

#define SM_FULL  0
#define SM_EMPTY 64
#define SM_RING  128

#define SWZ(b) ((b) ^ (((b) >> 3) & 0x70))

__device__ __align__(16) __half g_panh[KTAP - 1][MDIM * CIN];  // p1..p4 fp16 [M][8]
__device__ __align__(16) float  g_xT[MDIM * CIN];              // p0 fp32 [M][8]
__device__ __align__(16) __half g_L16[(size_t)MDIM * MDIM];

// ---------- helpers ----------
__device__ __forceinline__ uint32_t smem_u32(const void* p) {
    uint32_t a;
    asm("{ .reg .u64 t; cvta.to.shared.u64 t, %1; cvt.u32.u64 %0, t; }" : "=r"(a) : "l"(p));
    return a;
}
__device__ __forceinline__ unsigned long long pack2(float lo, float hi) {
    unsigned long long r;
    asm("mov.b64 %0, {%1, %2};" : "=l"(r) : "f"(lo), "f"(hi));
    return r;
}
__device__ __forceinline__ void unpack2(unsigned long long v, float& lo, float& hi) {
    asm("mov.b64 {%0, %1}, %2;" : "=f"(lo), "=f"(hi) : "l"(v));
}
__device__ __forceinline__ void fma2(unsigned long long& acc,
                                     unsigned long long a, unsigned long long b) {
    asm("fma.rn.f32x2 %0, %1, %2, %0;" : "+l"(acc) : "l"(a), "l"(b));
}
__device__ __forceinline__ void cp16(uint32_t dst, const void* src) {
    asm volatile("cp.async.cg.shared.global [%0], [%1], 16;" :: "r"(dst), "l"(src) : "memory");
}
__device__ __forceinline__ void cp_commit() {
    asm volatile("cp.async.commit_group;" ::: "memory");
}
template <int N>
__device__ __forceinline__ void cp_wait() {
    asm volatile("cp.async.wait_group %0;" :: "n"(N) : "memory");
}
__device__ __forceinline__ void mbar_init(uint32_t a, uint32_t cnt) {
    asm volatile("mbarrier.init.shared.b64 [%0], %1;" :: "r"(a), "r"(cnt) : "memory");
}
__device__ __forceinline__ void mbar_arrive(uint32_t a) {
    asm volatile("mbarrier.arrive.release.cta.shared::cta.b64 _, [%0];" :: "r"(a) : "memory");
}
__device__ __forceinline__ void mbar_wait_acq(uint32_t a, uint32_t ph) {
    asm volatile(
        "{\n\t.reg .pred P;\n\t"
        "WL%=:\n\t"
        "mbarrier.try_wait.parity.acquire.cta.shared::cta.b64 P, [%0], %1, 0x989680;\n\t"
        "@P bra.uni WD%=;\n\t"
        "bra.uni WL%=;\n\t"
        "WD%=:\n\t}"
        :: "r"(a), "r"(ph) : "memory");
}
__device__ __forceinline__ void ldsm_x4(uint32_t& r0, uint32_t& r1, uint32_t& r2,
                                        uint32_t& r3, uint32_t addr) {
    asm volatile("ldmatrix.sync.aligned.m8n8.x4.shared.b16 {%0,%1,%2,%3}, [%4];"
                 : "=r"(r0), "=r"(r1), "=r"(r2), "=r"(r3) : "r"(addr));
}
__device__ __forceinline__ void ldsm_x2t(uint32_t& r0, uint32_t& r1, uint32_t addr) {
    asm volatile("ldmatrix.sync.aligned.m8n8.x2.trans.shared.b16 {%0,%1}, [%2];"
                 : "=r"(r0), "=r"(r1) : "r"(addr));
}
__device__ __forceinline__ void mma16816(float& c0, float& c1, float& c2, float& c3,
                                         uint32_t a0, uint32_t a1, uint32_t a2, uint32_t a3,
                                         uint32_t b0, uint32_t b1) {
    asm volatile(
        "mma.sync.aligned.m16n8k16.row.col.f32.f16.f16.f32 "
        "{%0,%1,%2,%3}, {%4,%5,%6,%7}, {%8,%9}, {%0,%1,%2,%3};"
        : "+f"(c0), "+f"(c1), "+f"(c2), "+f"(c3)
        : "r"(a0), "r"(a1), "r"(a2), "r"(a3), "r"(b0), "r"(b1));
}

// xT[m*8 + i] = x[i*M + m]
__global__ __launch_bounds__(256)
void transpose_kernel(const float* __restrict__ x, float* __restrict__ xT) {
    const int m = blockIdx.x * blockDim.x + threadIdx.x;
    if (m >= MDIM) return;
    float v[CIN];
#pragma unroll
    for (int i = 0; i < CIN; ++i) v[i] = x[(size_t)i * MDIM + m];
    float4* dst = reinterpret_cast<float4*>(xT + (size_t)m * CIN);
    dst[0] = make_float4(v[0], v[1], v[2], v[3]);
    dst[1] = make_float4(v[4], v[5], v[6], v[7]);
}

// ============ step 1: fp32 L, fp32 FFMA, emits L16 shadow + fp16 p1 ============
__global__ __launch_bounds__(NTHR, 3)
void step32_kernel(const float* __restrict__ L,
                   const float* __restrict__ cur,
                   __half* __restrict__ nxt_h,
                   __half* __restrict__ L16out) {
    extern __shared__ __align__(128) unsigned char dsm[];
    const uint32_t smb = smem_u32(dsm);
    const int tid  = threadIdx.x;
    const int lane = tid & 31;
    const int w    = tid >> 5;
    const int m0   = blockIdx.x * RPB;

    if (tid == 0) {
#pragma unroll
        for (int s = 0; s < NS; ++s) {
            mbar_init(smb + SM_FULL  + 8 * s, 32);
            mbar_init(smb + SM_EMPTY + 8 * s, NWC);
        }
    }
    __syncthreads();

    if (w == NWC) {
        const unsigned char* curb = reinterpret_cast<const unsigned char*>(cur);
        int eph = 1;
        for (int u = 0; u < NSTG; ++u) {
            const int slot = u & (NS - 1);
            mbar_wait_acq(smb + SM_EMPTY + 8 * slot, (uint32_t)eph);
            const uint32_t dst0 = smb + SM_RING + slot * STAGE_B32;
            const int jb = u * SCOLS;                 // forward
#pragma unroll
            for (int r = 0; r < RPB; ++r) {
                int mr = m0 + r; if (mr > MDIM - 1) mr = MDIM - 1;
                cp16(dst0 + r * (SCOLS * 4) + lane * 16,
                     L + (size_t)mr * MDIM + jb + lane * 4);
            }
#pragma unroll
            for (int q = 0; q < 8; ++q) {
                const uint32_t off = (uint32_t)(lane * 16 + q * 512);
                cp16(dst0 + STAGE_L32 + SWZ(off),
                     curb + (size_t)jb * 32 + off);
            }
            cp_commit();
            if (u >= 2) { cp_wait<2>(); mbar_arrive(smb + SM_FULL + 8 * ((u - 2) & (NS - 1))); }
            if (slot == NS - 1) eph ^= 1;
        }
        cp_wait<1>(); mbar_arrive(smb + SM_FULL + 8 * ((NSTG - 2) & (NS - 1)));
        cp_wait<0>(); mbar_arrive(smb + SM_FULL + 8 * ((NSTG - 1) & (NS - 1)));
        return;
    }

    const int r0 = w * RPW;
    unsigned long long acc[RPW][NPAIR];
#pragma unroll
    for (int r = 0; r < RPW; ++r)
#pragma unroll
        for (int p = 0; p < NPAIR; ++p) acc[r][p] = 0ull;

    int fph = 0;
    for (int u = 0; u < NSTG; ++u) {
        const int slot = u & (NS - 1);
        mbar_wait_acq(smb + SM_FULL + 8 * slot, (uint32_t)fph);

        const unsigned char* lb = dsm + SM_RING + slot * STAGE_B32;
        float4 a[RPW];
#pragma unroll
        for (int r = 0; r < RPW; ++r)
            a[r] = *reinterpret_cast<const float4*>(
                       lb + (r0 + r) * (SCOLS * 4) + lane * 16);

        // emit fp16 shadow of L
        const int jc = u * SCOLS + 4 * lane;
#pragma unroll
        for (int r = 0; r < RPW; ++r) {
            const int m = m0 + r0 + r;
            if (m < MDIM) {
                __half2 h01 = __floats2half2_rn(a[r].x, a[r].y);
                __half2 h23 = __floats2half2_rn(a[r].z, a[r].w);
                uint2 pkd;
                pkd.x = *reinterpret_cast<uint32_t*>(&h01);
                pkd.y = *reinterpret_cast<uint32_t*>(&h23);
                *reinterpret_cast<uint2*>(L16out + (size_t)m * MDIM + jc) = pkd;
            }
        }

        const unsigned char* pbp = lb + STAGE_L32;
#pragma unroll
        for (int jj = 0; jj < 4; ++jj) {
            const int jl = 4 * lane + jj;
            ulonglong2 q0 = *reinterpret_cast<const ulonglong2*>(pbp + SWZ(jl * 32));
            ulonglong2 q1 = *reinterpret_cast<const ulonglong2*>(pbp + SWZ(jl * 32 + 16));
#pragma unroll
            for (int r = 0; r < RPW; ++r) {
                float av = (jj == 0) ? a[r].x : (jj == 1) ? a[r].y
                         : (jj == 2) ? a[r].z : a[r].w;
                unsigned long long aa = pack2(av, av);
                fma2(acc[r][0], aa, q0.x);
                fma2(acc[r][1], aa, q0.y);
                fma2(acc[r][2], aa, q1.x);
                fma2(acc[r][3], aa, q1.y);
            }
        }

        if (lane == 0) mbar_arrive(smb + SM_EMPTY + 8 * slot);
        if (slot == NS - 1) fph ^= 1;
    }

#pragma unroll
    for (int r = 0; r < RPW; ++r) {
        const int m = m0 + r0 + r;
        float ov[CIN];
#pragma unroll
        for (int p = 0; p < NPAIR; ++p) {
            float v0, v1;
            unpack2(acc[r][p], v0, v1);
#pragma unroll
            for (int d = 16; d > 0; d >>= 1) {
                v0 += __shfl_down_sync(0xffffffffu, v0, d);
                v1 += __shfl_down_sync(0xffffffffu, v1, d);
            }
            ov[2 * p] = v0; ov[2 * p + 1] = v1;
        }
        if (lane == 0 && m < MDIM) {
            __half2 h0 = __floats2half2_rn(ov[0], ov[1]);
            __half2 h1 = __floats2half2_rn(ov[2], ov[3]);
            __half2 h2 = __floats2half2_rn(ov[4], ov[5]);
            __half2 h3 = __floats2half2_rn(ov[6], ov[7]);
            uint4 pkd;
            pkd.x = *reinterpret_cast<uint32_t*>(&h0);
            pkd.y = *reinterpret_cast<uint32_t*>(&h1);
            pkd.z = *reinterpret_cast<uint32_t*>(&h2);
            pkd.w = *reinterpret_cast<uint32_t*>(&h3);
            *reinterpret_cast<uint4*>(nxt_h + (size_t)m * CIN) = pkd;
        }
    }
}

// ============ steps 2-4: fp16 L shadow + fp16 panel, HMMA m16n8k16 ============
__global__ __launch_bounds__(NTHR, 3)
void step16_kernel(const __half* __restrict__ Lh,
                   const __half* __restrict__ cur_h,
                   __half* __restrict__ nxt_h,
                   int dir) {
    extern __shared__ __align__(128) unsigned char dsm[];
    const uint32_t smb = smem_u32(dsm);
    const int tid  = threadIdx.x;
    const int lane = tid & 31;
    const int w    = tid >> 5;
    const int m0   = blockIdx.x * MROWS;

    if (tid == 0) {
#pragma unroll
        for (int s = 0; s < NS; ++s) {
            mbar_init(smb + SM_FULL  + 8 * s, 32);
            mbar_init(smb + SM_EMPTY + 8 * s, NWC);
        }
    }
    __syncthreads();

    if (w == NWC) {
        // ================= producer warp =================
        int eph = 1;
        for (int u = 0; u < NSTG; ++u) {
            const int t    = dir ? (NSTG - 1 - u) : u;
            const int slot = u & (NS - 1);
            mbar_wait_acq(smb + SM_EMPTY + 8 * slot, (uint32_t)eph);
            const uint32_t dst0 = smb + SM_RING + slot * M_STAGE_B;
            const int jb = t * SCOLS;
            // L16: 64 rows x 256 B, ldmatrix-friendly 16B-chunk swizzle.
            const int c = lane & 15;
#pragma unroll
            for (int rr = 0; rr < 32; ++rr) {
                const int r = 2 * rr + (lane >> 4);            // local row 0..63
                const uint32_t phys = (uint32_t)(r * 256 + ((c & 8) << 4)
                                                 + (((c ^ r) & 7) << 4));
                cp16(dst0 + phys,
                     Lh + (size_t)(m0 + r) * MDIM + jb + c * 8);
            }
            // panel: 128 rows x 16 B fp16, linear
#pragma unroll
            for (int q = 0; q < 4; ++q) {
                const int j = q * 32 + lane;
                cp16(dst0 + M_STAGE_L + j * 16,
                     cur_h + (size_t)(jb + j) * CIN);
            }
            cp_commit();
            if (u >= 2) { cp_wait<2>(); mbar_arrive(smb + SM_FULL + 8 * ((u - 2) & (NS - 1))); }
            if (slot == NS - 1) eph ^= 1;
        }
        cp_wait<1>(); mbar_arrive(smb + SM_FULL + 8 * ((NSTG - 2) & (NS - 1)));
        cp_wait<0>(); mbar_arrive(smb + SM_FULL + 8 * ((NSTG - 1) & (NS - 1)));
        return;
    }

    // ================= mma warps (16 rows each) =================
    float c0 = 0.f, c1 = 0.f, c2 = 0.f, c3 = 0.f;
    const uint32_t arow = (uint32_t)(w * 16 + (lane & 15));   // local stage row
    const uint32_t ca   = (uint32_t)(lane >> 4);              // 0/1: k half

    int fph = 0;
    for (int u = 0; u < NSTG; ++u) {
        const int slot = u & (NS - 1);
        mbar_wait_acq(smb + SM_FULL + 8 * slot, (uint32_t)fph);

        const uint32_t lbase = smb + SM_RING + slot * M_STAGE_B;
        const uint32_t pbase = lbase + M_STAGE_L;
#pragma unroll
        for (int kb = 0; kb < 8; ++kb) {
            const uint32_t c = 2 * kb + ca;
            const uint32_t addrA = lbase + arow * 256 + ((c & 8) << 4)
                                   + (((c ^ arow) & 7) << 4);
            uint32_t a0, a1, a2, a3;
            ldsm_x4(a0, a1, a2, a3, addrA);
            const uint32_t addrB = pbase + (kb * 16 + (lane & 15)) * 16;
            uint32_t b0, b1;
            ldsm_x2t(b0, b1, addrB);
            mma16816(c0, c1, c2, c3, a0, a1, a2, a3, b0, b1);
        }

        if (lane == 0) mbar_arrive(smb + SM_EMPTY + 8 * slot);
        if (slot == NS - 1) fph ^= 1;
    }

    // epilogue: C[16x8] -> fp16 panel rows
    {
        const int row0 = m0 + w * 16 + (lane >> 2);
        const int n0   = (lane & 3) * 2;
        __half2 h0 = __floats2half2_rn(c0, c1);
        __half2 h1 = __floats2half2_rn(c2, c3);
        *reinterpret_cast<uint32_t*>(nxt_h + (size_t)row0 * CIN + n0) =
            *reinterpret_cast<uint32_t*>(&h0);
        *reinterpret_cast<uint32_t*>(nxt_h + (size_t)(row0 + 8) * CIN + n0) =
            *reinterpret_cast<uint32_t*>(&h1);
    }
}

// y[o][m] = bias[o] + sum_{i,k} theta[o][i][k] * P[k][m][i]
__global__ __launch_bounds__(256)
void mix_kernel(const float* __restrict__ x,
                const float* __restrict__ theta,
                const float* __restrict__ bias,
                float* __restrict__ out) {
    __shared__ float th[COUT * CIN * KTAP];
    __shared__ float bs[COUT];
    const int tid = threadIdx.x;
    for (int idx = tid; idx < COUT * CIN * KTAP; idx += blockDim.x)
        th[idx] = theta[idx];
    if (tid < COUT) bs[tid] = bias[tid];
    __syncthreads();

    const int m = blockIdx.x * blockDim.x + tid;
    if (m >= MDIM) return;

    float p[KTAP][CIN];
#pragma unroll
    for (int i = 0; i < CIN; ++i) p[0][i] = x[(size_t)i * MDIM + m];
#pragma unroll
    for (int k = 1; k < KTAP; ++k) {
        const uint2* src = reinterpret_cast<const uint2*>(
                               &g_panh[k - 1][(size_t)m * CIN]);
        uint2 lo = src[0], hi = src[1];
        float2 f0 = __half22float2(*reinterpret_cast<__half2*>(&lo.x));
        float2 f1 = __half22float2(*reinterpret_cast<__half2*>(&lo.y));
        float2 f2 = __half22float2(*reinterpret_cast<__half2*>(&hi.x));
        float2 f3 = __half22float2(*reinterpret_cast<__half2*>(&hi.y));
        p[k][0] = f0.x; p[k][1] = f0.y; p[k][2] = f1.x; p[k][3] = f1.y;
        p[k][4] = f2.x; p[k][5] = f2.y; p[k][6] = f3.x; p[k][7] = f3.y;
    }

#pragma unroll
    for (int o = 0; o < COUT; ++o) {
        float s = bs[o];
#pragma unroll
        for (int i = 0; i < CIN; ++i)
#pragma unroll
            for (int k = 0; k < KTAP; ++k)
                s += th[(o * CIN + i) * KTAP + k] * p[k][i];
        out[(size_t)o * MDIM + m] = s;
    }
}

extern "C" void kernel_launch(void* const* d_in, const int* in_sizes, int n_in,
                              void* d_out, int out_size) {
    const float* L     = (const float*)d_in[0];
    const float* x     = (const float*)d_in[1];
    const float* theta = (const float*)d_in[2];
    const float* bias  = (const float*)d_in[3];
    float* out = (float*)d_out;

    cudaFuncSetAttribute(step32_kernel,
                         cudaFuncAttributeMaxDynamicSharedMemorySize, SMEM32);
    cudaFuncSetAttribute(step16_kernel,
                         cudaFuncAttributeMaxDynamicSharedMemorySize, SMEM16);

    __half* panh = nullptr;
    cudaGetSymbolAddress((void**)&panh, g_panh);
    float* xT = nullptr;
    cudaGetSymbolAddress((void**)&xT, g_xT);
    __half* L16 = nullptr;
    cudaGetSymbolAddress((void**)&L16, g_L16);

    const size_t PSZ = (size_t)MDIM * CIN;

    transpose_kernel<<<(MDIM + 255) / 256, 256>>>(x, xT);
    // Step 1: fp32 L (forward), emits fp16 shadow + fp16 p1.
    step32_kernel<<<GRID32, NTHR, SMEM32>>>(L, xT, panh + 0 * PSZ, L16);
    // Steps 2-4: tensor-core fp16, serpentine (step 2 reversed hits the
    // L2 residue of step 1's shadow writes).
    step16_kernel<<<GRID16, NTHR, SMEM16>>>(L16, panh + 0 * PSZ, panh + 1 * PSZ, 1);
    step16_kernel<<<GRID16, NTHR, SMEM16>>>(L16, panh + 1 * PSZ, panh + 2 * PSZ, 0);
    step16_kernel<<<GRID16, NTHR, SMEM16>>>(L16, panh + 2 * PSZ, panh + 3 * PSZ, 1);

    mix_kernel<<<(MDIM + 255) / 256, 256>>>(x, theta, bias, out);
}

// round 15
// speedup vs baseline: 1.3270x; 1.0606x over previous
#include <cuda_runtime.h>
#include <cuda_fp16.h>
#include <cstdint>

#define MDIM 12288
#define CIN 8
#define NPAIR 4
#define COUT 16
#define KTAP 5

// ---------- step32 (step 1) geometry: R11 winner ----------
#define RPW 7
#define NWC32 4
#define RPB (RPW * NWC32)        // 28
#define NCTHR (NWC32 * 32)
#define NTHR32 (NCTHR + 32)      // 160
#define GRID32 439

#define SCOLS 128
#define NS32 4
#define NSTG (MDIM / SCOLS)      // 96
#define STAGE_L32 (RPB * SCOLS * 4)      // 14336
#define STAGE_P32 (SCOLS * CIN * 4)      // 4096
#define STAGE_B32 (STAGE_L32 + STAGE_P32)
#define SMEM32 (128 + NS32 * STAGE_B32)  // 73856

// ---------- step16 MMA geometry (rebalanced) ----------
#define MROWS 32                 // rows per CTA (2 mma warps x 16)
#define GRID16 (MDIM / MROWS)    // 384  (single wave: <= 3*148)
#define NWC16 2                  // mma warps
#define NTHR16 ((NWC16 + 1) * 32)    // 96
#define NS16 6                   // ring depth
#define LAG 4                    // cp.async publish lag (in-flight stages)
#define M_STAGE_L (MROWS * SCOLS * 2)    // 8192 (fp16, 256B/row, swizzled)
#define M_STAGE_P (SCOLS * CIN * 2)      // 2048 (fp16 panel, linear)
#define M_STAGE_B (M_STAGE_L + M_STAGE_P)  // 10240
#define SMEM16 (128 + NS16 * M_STAGE_B)  // 61568 -> 3 CTAs/SM

#define SM_FULL  0
#define SM_EMPTY 64
#define SM_RING  128

#define SWZ(b) ((b) ^ (((b) >> 3) & 0x70))

__device__ __align__(16) __half g_panh[KTAP - 1][MDIM * CIN];  // p1..p4 fp16 [M][8]
__device__ __align__(16) float  g_xT[MDIM * CIN];              // p0 fp32 [M][8]
__device__ __align__(16) __half g_L16[(size_t)MDIM * MDIM];

// ---------- helpers ----------
__device__ __forceinline__ uint32_t smem_u32(const void* p) {
    uint32_t a;
    asm("{ .reg .u64 t; cvta.to.shared.u64 t, %1; cvt.u32.u64 %0, t; }" : "=r"(a) : "l"(p));
    return a;
}
__device__ __forceinline__ unsigned long long pack2(float lo, float hi) {
    unsigned long long r;
    asm("mov.b64 %0, {%1, %2};" : "=l"(r) : "f"(lo), "f"(hi));
    return r;
}
__device__ __forceinline__ void unpack2(unsigned long long v, float& lo, float& hi) {
    asm("mov.b64 {%0, %1}, %2;" : "=f"(lo), "=f"(hi) : "l"(v));
}
__device__ __forceinline__ void fma2(unsigned long long& acc,
                                     unsigned long long a, unsigned long long b) {
    asm("fma.rn.f32x2 %0, %1, %2, %0;" : "+l"(acc) : "l"(a), "l"(b));
}
__device__ __forceinline__ void cp16(uint32_t dst, const void* src) {
    asm volatile("cp.async.cg.shared.global [%0], [%1], 16;" :: "r"(dst), "l"(src) : "memory");
}
__device__ __forceinline__ void cp_commit() {
    asm volatile("cp.async.commit_group;" ::: "memory");
}
template <int N>
__device__ __forceinline__ void cp_wait() {
    asm volatile("cp.async.wait_group %0;" :: "n"(N) : "memory");
}
__device__ __forceinline__ void mbar_init(uint32_t a, uint32_t cnt) {
    asm volatile("mbarrier.init.shared.b64 [%0], %1;" :: "r"(a), "r"(cnt) : "memory");
}
__device__ __forceinline__ void mbar_arrive(uint32_t a) {
    asm volatile("mbarrier.arrive.release.cta.shared::cta.b64 _, [%0];" :: "r"(a) : "memory");
}
__device__ __forceinline__ void mbar_wait_acq(uint32_t a, uint32_t ph) {
    asm volatile(
        "{\n\t.reg .pred P;\n\t"
        "WL%=:\n\t"
        "mbarrier.try_wait.parity.acquire.cta.shared::cta.b64 P, [%0], %1, 0x989680;\n\t"
        "@P bra.uni WD%=;\n\t"
        "bra.uni WL%=;\n\t"
        "WD%=:\n\t}"
        :: "r"(a), "r"(ph) : "memory");
}
__device__ __forceinline__ void ldsm_x4(uint32_t& r0, uint32_t& r1, uint32_t& r2,
                                        uint32_t& r3, uint32_t addr) {
    asm volatile("ldmatrix.sync.aligned.m8n8.x4.shared.b16 {%0,%1,%2,%3}, [%4];"
                 : "=r"(r0), "=r"(r1), "=r"(r2), "=r"(r3) : "r"(addr));
}
__device__ __forceinline__ void ldsm_x2t(uint32_t& r0, uint32_t& r1, uint32_t addr) {
    asm volatile("ldmatrix.sync.aligned.m8n8.x2.trans.shared.b16 {%0,%1}, [%2];"
                 : "=r"(r0), "=r"(r1) : "r"(addr));
}
__device__ __forceinline__ void mma16816(float& c0, float& c1, float& c2, float& c3,
                                         uint32_t a0, uint32_t a1, uint32_t a2, uint32_t a3,
                                         uint32_t b0, uint32_t b1) {
    asm volatile(
        "mma.sync.aligned.m16n8k16.row.col.f32.f16.f16.f32 "
        "{%0,%1,%2,%3}, {%4,%5,%6,%7}, {%8,%9}, {%0,%1,%2,%3};"
        : "+f"(c0), "+f"(c1), "+f"(c2), "+f"(c3)
        : "r"(a0), "r"(a1), "r"(a2), "r"(a3), "r"(b0), "r"(b1));
}

// xT[m*8 + i] = x[i*M + m]
__global__ __launch_bounds__(256)
void transpose_kernel(const float* __restrict__ x, float* __restrict__ xT) {
    const int m = blockIdx.x * blockDim.x + threadIdx.x;
    if (m >= MDIM) return;
    float v[CIN];
#pragma unroll
    for (int i = 0; i < CIN; ++i) v[i] = x[(size_t)i * MDIM + m];
    float4* dst = reinterpret_cast<float4*>(xT + (size_t)m * CIN);
    dst[0] = make_float4(v[0], v[1], v[2], v[3]);
    dst[1] = make_float4(v[4], v[5], v[6], v[7]);
}

// ============ step 1: fp32 L, fp32 FFMA, emits L16 shadow + fp16 p1 ============
__global__ __launch_bounds__(NTHR32, 3)
void step32_kernel(const float* __restrict__ L,
                   const float* __restrict__ cur,
                   __half* __restrict__ nxt_h,
                   __half* __restrict__ L16out) {
    extern __shared__ __align__(128) unsigned char dsm[];
    const uint32_t smb = smem_u32(dsm);
    const int tid  = threadIdx.x;
    const int lane = tid & 31;
    const int w    = tid >> 5;
    const int m0   = blockIdx.x * RPB;

    if (tid == 0) {
#pragma unroll
        for (int s = 0; s < NS32; ++s) {
            mbar_init(smb + SM_FULL  + 8 * s, 32);
            mbar_init(smb + SM_EMPTY + 8 * s, NWC32);
        }
    }
    __syncthreads();

    if (w == NWC32) {
        const unsigned char* curb = reinterpret_cast<const unsigned char*>(cur);
        int eph = 1;
        for (int u = 0; u < NSTG; ++u) {
            const int slot = u & (NS32 - 1);
            mbar_wait_acq(smb + SM_EMPTY + 8 * slot, (uint32_t)eph);
            const uint32_t dst0 = smb + SM_RING + slot * STAGE_B32;
            const int jb = u * SCOLS;                 // forward
#pragma unroll
            for (int r = 0; r < RPB; ++r) {
                int mr = m0 + r; if (mr > MDIM - 1) mr = MDIM - 1;
                cp16(dst0 + r * (SCOLS * 4) + lane * 16,
                     L + (size_t)mr * MDIM + jb + lane * 4);
            }
#pragma unroll
            for (int q = 0; q < 8; ++q) {
                const uint32_t off = (uint32_t)(lane * 16 + q * 512);
                cp16(dst0 + STAGE_L32 + SWZ(off),
                     curb + (size_t)jb * 32 + off);
            }
            cp_commit();
            if (u >= 2) { cp_wait<2>(); mbar_arrive(smb + SM_FULL + 8 * ((u - 2) & (NS32 - 1))); }
            if (slot == NS32 - 1) eph ^= 1;
        }
        cp_wait<1>(); mbar_arrive(smb + SM_FULL + 8 * ((NSTG - 2) & (NS32 - 1)));
        cp_wait<0>(); mbar_arrive(smb + SM_FULL + 8 * ((NSTG - 1) & (NS32 - 1)));
        return;
    }

    const int r0 = w * RPW;
    unsigned long long acc[RPW][NPAIR];
#pragma unroll
    for (int r = 0; r < RPW; ++r)
#pragma unroll
        for (int p = 0; p < NPAIR; ++p) acc[r][p] = 0ull;

    int fph = 0;
    for (int u = 0; u < NSTG; ++u) {
        const int slot = u & (NS32 - 1);
        mbar_wait_acq(smb + SM_FULL + 8 * slot, (uint32_t)fph);

        const unsigned char* lb = dsm + SM_RING + slot * STAGE_B32;
        float4 a[RPW];
#pragma unroll
        for (int r = 0; r < RPW; ++r)
            a[r] = *reinterpret_cast<const float4*>(
                       lb + (r0 + r) * (SCOLS * 4) + lane * 16);

        // emit fp16 shadow of L
        const int jc = u * SCOLS + 4 * lane;
#pragma unroll
        for (int r = 0; r < RPW; ++r) {
            const int m = m0 + r0 + r;
            if (m < MDIM) {
                __half2 h01 = __floats2half2_rn(a[r].x, a[r].y);
                __half2 h23 = __floats2half2_rn(a[r].z, a[r].w);
                uint2 pkd;
                pkd.x = *reinterpret_cast<uint32_t*>(&h01);
                pkd.y = *reinterpret_cast<uint32_t*>(&h23);
                *reinterpret_cast<uint2*>(L16out + (size_t)m * MDIM + jc) = pkd;
            }
        }

        const unsigned char* pbp = lb + STAGE_L32;
#pragma unroll
        for (int jj = 0; jj < 4; ++jj) {
            const int jl = 4 * lane + jj;
            ulonglong2 q0 = *reinterpret_cast<const ulonglong2*>(pbp + SWZ(jl * 32));
            ulonglong2 q1 = *reinterpret_cast<const ulonglong2*>(pbp + SWZ(jl * 32 + 16));
#pragma unroll
            for (int r = 0; r < RPW; ++r) {
                float av = (jj == 0) ? a[r].x : (jj == 1) ? a[r].y
                         : (jj == 2) ? a[r].z : a[r].w;
                unsigned long long aa = pack2(av, av);
                fma2(acc[r][0], aa, q0.x);
                fma2(acc[r][1], aa, q0.y);
                fma2(acc[r][2], aa, q1.x);
                fma2(acc[r][3], aa, q1.y);
            }
        }

        if (lane == 0) mbar_arrive(smb + SM_EMPTY + 8 * slot);
        if (slot == NS32 - 1) fph ^= 1;
    }

#pragma unroll
    for (int r = 0; r < RPW; ++r) {
        const int m = m0 + r0 + r;
        float ov[CIN];
#pragma unroll
        for (int p = 0; p < NPAIR; ++p) {
            float v0, v1;
            unpack2(acc[r][p], v0, v1);
#pragma unroll
            for (int d = 16; d > 0; d >>= 1) {
                v0 += __shfl_down_sync(0xffffffffu, v0, d);
                v1 += __shfl_down_sync(0xffffffffu, v1, d);
            }
            ov[2 * p] = v0; ov[2 * p + 1] = v1;
        }
        if (lane == 0 && m < MDIM) {
            __half2 h0 = __floats2half2_rn(ov[0], ov[1]);
            __half2 h1 = __floats2half2_rn(ov[2], ov[3]);
            __half2 h2 = __floats2half2_rn(ov[4], ov[5]);
            __half2 h3 = __floats2half2_rn(ov[6], ov[7]);
            uint4 pkd;
            pkd.x = *reinterpret_cast<uint32_t*>(&h0);
            pkd.y = *reinterpret_cast<uint32_t*>(&h1);
            pkd.z = *reinterpret_cast<uint32_t*>(&h2);
            pkd.w = *reinterpret_cast<uint32_t*>(&h3);
            *reinterpret_cast<uint4*>(nxt_h + (size_t)m * CIN) = pkd;
        }
    }
}

// ============ steps 2-4: fp16 HMMA, 32 rows/CTA, single-wave grid ============
__global__ __launch_bounds__(NTHR16, 3)
void step16_kernel(const __half* __restrict__ Lh,
                   const __half* __restrict__ cur_h,
                   __half* __restrict__ nxt_h,
                   int dir) {
    extern __shared__ __align__(128) unsigned char dsm[];
    const uint32_t smb = smem_u32(dsm);
    const int tid  = threadIdx.x;
    const int lane = tid & 31;
    const int w    = tid >> 5;
    const int m0   = blockIdx.x * MROWS;

    if (tid == 0) {
#pragma unroll
        for (int s = 0; s < NS16; ++s) {
            mbar_init(smb + SM_FULL  + 8 * s, 32);
            mbar_init(smb + SM_EMPTY + 8 * s, NWC16);
        }
    }
    __syncthreads();

    if (w == NWC16) {
        // ================= producer warp =================
        int slot = 0, eph = 1;
        for (int u = 0; u < NSTG; ++u) {
            const int t = dir ? (NSTG - 1 - u) : u;
            mbar_wait_acq(smb + SM_EMPTY + 8 * slot, (uint32_t)eph);
            const uint32_t dst0 = smb + SM_RING + slot * M_STAGE_B;
            const int jb = t * SCOLS;
            // L16: 32 rows x 256 B, ldmatrix-friendly 16B-chunk swizzle.
            const int c = lane & 15;
#pragma unroll
            for (int rr = 0; rr < MROWS / 2; ++rr) {
                const int r = 2 * rr + (lane >> 4);            // local row 0..31
                const uint32_t phys = (uint32_t)(r * 256 + ((c & 8) << 4)
                                                 + (((c ^ r) & 7) << 4));
                cp16(dst0 + phys,
                     Lh + (size_t)(m0 + r) * MDIM + jb + c * 8);
            }
            // panel: 128 rows x 16 B fp16, linear
#pragma unroll
            for (int q = 0; q < 4; ++q) {
                const int j = q * 32 + lane;
                cp16(dst0 + M_STAGE_L + j * 16,
                     cur_h + (size_t)(jb + j) * CIN);
            }
            cp_commit();
            if (u >= LAG) {
                cp_wait<LAG>();
                int ps = u - LAG;
                int pslot = ps % NS16;
                mbar_arrive(smb + SM_FULL + 8 * pslot);
            }
            if (++slot == NS16) { slot = 0; eph ^= 1; }
        }
        cp_wait<3>(); mbar_arrive(smb + SM_FULL + 8 * ((NSTG - 4) % NS16));
        cp_wait<2>(); mbar_arrive(smb + SM_FULL + 8 * ((NSTG - 3) % NS16));
        cp_wait<1>(); mbar_arrive(smb + SM_FULL + 8 * ((NSTG - 2) % NS16));
        cp_wait<0>(); mbar_arrive(smb + SM_FULL + 8 * ((NSTG - 1) % NS16));
        return;
    }

    // ================= mma warps (16 rows each) =================
    float c0 = 0.f, c1 = 0.f, c2 = 0.f, c3 = 0.f;
    const uint32_t arow = (uint32_t)(w * 16 + (lane & 15));   // local stage row
    const uint32_t ca   = (uint32_t)(lane >> 4);              // 0/1: k half

    int slot = 0, fph = 0;
    for (int u = 0; u < NSTG; ++u) {
        mbar_wait_acq(smb + SM_FULL + 8 * slot, (uint32_t)fph);

        const uint32_t lbase = smb + SM_RING + slot * M_STAGE_B;
        const uint32_t pbase = lbase + M_STAGE_L;
#pragma unroll
        for (int kb = 0; kb < 8; ++kb) {
            const uint32_t c = 2 * kb + ca;
            const uint32_t addrA = lbase + arow * 256 + ((c & 8) << 4)
                                   + (((c ^ arow) & 7) << 4);
            uint32_t a0, a1, a2, a3;
            ldsm_x4(a0, a1, a2, a3, addrA);
            const uint32_t addrB = pbase + (kb * 16 + (lane & 15)) * 16;
            uint32_t b0, b1;
            ldsm_x2t(b0, b1, addrB);
            mma16816(c0, c1, c2, c3, a0, a1, a2, a3, b0, b1);
        }

        if (lane == 0) mbar_arrive(smb + SM_EMPTY + 8 * slot);
        if (++slot == NS16) { slot = 0; fph ^= 1; }
    }

    // epilogue: C[16x8] -> fp16 panel rows
    {
        const int row0 = m0 + w * 16 + (lane >> 2);
        const int n0   = (lane & 3) * 2;
        __half2 h0 = __floats2half2_rn(c0, c1);
        __half2 h1 = __floats2half2_rn(c2, c3);
        *reinterpret_cast<uint32_t*>(nxt_h + (size_t)row0 * CIN + n0) =
            *reinterpret_cast<uint32_t*>(&h0);
        *reinterpret_cast<uint32_t*>(nxt_h + (size_t)(row0 + 8) * CIN + n0) =
            *reinterpret_cast<uint32_t*>(&h1);
    }
}

// y[o][m] = bias[o] + sum_{i,k} theta[o][i][k] * P[k][m][i]
__global__ __launch_bounds__(256)
void mix_kernel(const float* __restrict__ x,
                const float* __restrict__ theta,
                const float* __restrict__ bias,
                float* __restrict__ out) {
    __shared__ float th[COUT * CIN * KTAP];
    __shared__ float bs[COUT];
    const int tid = threadIdx.x;
    for (int idx = tid; idx < COUT * CIN * KTAP; idx += blockDim.x)
        th[idx] = theta[idx];
    if (tid < COUT) bs[tid] = bias[tid];
    __syncthreads();

    const int m = blockIdx.x * blockDim.x + tid;
    if (m >= MDIM) return;

    float p[KTAP][CIN];
#pragma unroll
    for (int i = 0; i < CIN; ++i) p[0][i] = x[(size_t)i * MDIM + m];
#pragma unroll
    for (int k = 1; k < KTAP; ++k) {
        const uint2* src = reinterpret_cast<const uint2*>(
                               &g_panh[k - 1][(size_t)m * CIN]);
        uint2 lo = src[0], hi = src[1];
        float2 f0 = __half22float2(*reinterpret_cast<__half2*>(&lo.x));
        float2 f1 = __half22float2(*reinterpret_cast<__half2*>(&lo.y));
        float2 f2 = __half22float2(*reinterpret_cast<__half2*>(&hi.x));
        float2 f3 = __half22float2(*reinterpret_cast<__half2*>(&hi.y));
        p[k][0] = f0.x; p[k][1] = f0.y; p[k][2] = f1.x; p[k][3] = f1.y;
        p[k][4] = f2.x; p[k][5] = f2.y; p[k][6] = f3.x; p[k][7] = f3.y;
    }

#pragma unroll
    for (int o = 0; o < COUT; ++o) {
        float s = bs[o];
#pragma unroll
        for (int i = 0; i < CIN; ++i)
#pragma unroll
            for (int k = 0; k < KTAP; ++k)
                s += th[(o * CIN + i) * KTAP + k] * p[k][i];
        out[(size_t)o * MDIM + m] = s;
    }
}

extern "C" void kernel_launch(void* const* d_in, const int* in_sizes, int n_in,
                              void* d_out, int out_size) {
    const float* L     = (const float*)d_in[0];
    const float* x     = (const float*)d_in[1];
    const float* theta = (const float*)d_in[2];
    const float* bias  = (const float*)d_in[3];
    float* out = (float*)d_out;

    cudaFuncSetAttribute(step32_kernel,
                         cudaFuncAttributeMaxDynamicSharedMemorySize, SMEM32);
    cudaFuncSetAttribute(step16_kernel,
                         cudaFuncAttributeMaxDynamicSharedMemorySize, SMEM16);

    __half* panh = nullptr;
    cudaGetSymbolAddress((void**)&panh, g_panh);
    float* xT = nullptr;
    cudaGetSymbolAddress((void**)&xT, g_xT);
    __half* L16 = nullptr;
    cudaGetSymbolAddress((void**)&L16, g_L16);

    const size_t PSZ = (size_t)MDIM * CIN;

    transpose_kernel<<<(MDIM + 255) / 256, 256>>>(x, xT);
    // Step 1: fp32 L (forward), emits fp16 shadow + fp16 p1.
    step32_kernel<<<GRID32, NTHR32, SMEM32>>>(L, xT, panh + 0 * PSZ, L16);
    // Steps 2-4: tensor-core fp16, single-wave grid, serpentine.
    step16_kernel<<<GRID16, NTHR16, SMEM16>>>(L16, panh + 0 * PSZ, panh + 1 * PSZ, 1);
    step16_kernel<<<GRID16, NTHR16, SMEM16>>>(L16, panh + 1 * PSZ, panh + 2 * PSZ, 0);
    step16_kernel<<<GRID16, NTHR16, SMEM16>>>(L16, panh + 2 * PSZ, panh + 3 * PSZ, 1);

    mix_kernel<<<(MDIM + 255) / 256, 256>>>(x, theta, bias, out);
}

// round 16
// speedup vs baseline: 1.3548x; 1.0209x over previous
#include <cuda_runtime.h>
#include <cuda_fp16.h>
#include <cstdint>

#define MDIM 12288
#define CIN 8
#define NPAIR 4
#define COUT 16
#define KTAP 5

// ---------- step32 (step 1) geometry: R11 winner ----------
#define RPW 7
#define NWC32 4
#define RPB (RPW * NWC32)        // 28
#define NCTHR (NWC32 * 32)
#define NTHR32 (NCTHR + 32)      // 160
#define GRID32 439

#define SCOLS 128
#define NS32 4
#define NSTG (MDIM / SCOLS)      // 96
#define STAGE_L32 (RPB * SCOLS * 4)      // 14336
#define STAGE_P32 (SCOLS * CIN * 4)      // 4096
#define STAGE_B32 (STAGE_L32 + STAGE_P32)
#define SMEM32 (128 + NS32 * STAGE_B32)  // 73856

// ---------- step16 MMA geometry ----------
#define MROWS 32                 // rows per CTA (2 mma warps x 16)
#define GRID16 (MDIM / MROWS)    // 384  (single wave: <= 3*148 -> co-resident)
#define NWC16 2
#define NTHR16 ((NWC16 + 1) * 32)    // 96
#define NS16 6
#define LAG 4
#define M_STAGE_L (MROWS * SCOLS * 2)    // 8192
#define M_STAGE_P (SCOLS * CIN * 2)      // 2048
#define M_STAGE_B (M_STAGE_L + M_STAGE_P)  // 10240
#define SMEM16 (128 + NS16 * M_STAGE_B)  // 61568 -> 3 CTAs/SM

#define SM_FULL  0
#define SM_EMPTY 64
#define SM_RING  128

#define SWZ(b) ((b) ^ (((b) >> 3) & 0x70))

__device__ __align__(16) __half g_panh[KTAP - 1][MDIM * CIN];  // p1..p4 fp16 [M][8]
__device__ __align__(16) float  g_xT[MDIM * CIN];
__device__ __align__(16) __half g_L16[(size_t)MDIM * MDIM];
__device__ unsigned g_bar = 0;   // monotone grid-barrier ticket counter

// ---------- helpers ----------
__device__ __forceinline__ uint32_t smem_u32(const void* p) {
    uint32_t a;
    asm("{ .reg .u64 t; cvta.to.shared.u64 t, %1; cvt.u32.u64 %0, t; }" : "=r"(a) : "l"(p));
    return a;
}
__device__ __forceinline__ unsigned long long pack2(float lo, float hi) {
    unsigned long long r;
    asm("mov.b64 %0, {%1, %2};" : "=l"(r) : "f"(lo), "f"(hi));
    return r;
}
__device__ __forceinline__ void unpack2(unsigned long long v, float& lo, float& hi) {
    asm("mov.b64 {%0, %1}, %2;" : "=f"(lo), "=f"(hi) : "l"(v));
}
__device__ __forceinline__ void fma2(unsigned long long& acc,
                                     unsigned long long a, unsigned long long b) {
    asm("fma.rn.f32x2 %0, %1, %2, %0;" : "+l"(acc) : "l"(a), "l"(b));
}
__device__ __forceinline__ void cp16(uint32_t dst, const void* src) {
    asm volatile("cp.async.cg.shared.global [%0], [%1], 16;" :: "r"(dst), "l"(src) : "memory");
}
__device__ __forceinline__ void cp_commit() {
    asm volatile("cp.async.commit_group;" ::: "memory");
}
template <int N>
__device__ __forceinline__ void cp_wait() {
    asm volatile("cp.async.wait_group %0;" :: "n"(N) : "memory");
}
__device__ __forceinline__ void mbar_init(uint32_t a, uint32_t cnt) {
    asm volatile("mbarrier.init.shared.b64 [%0], %1;" :: "r"(a), "r"(cnt) : "memory");
}
__device__ __forceinline__ void mbar_arrive(uint32_t a) {
    asm volatile("mbarrier.arrive.release.cta.shared::cta.b64 _, [%0];" :: "r"(a) : "memory");
}
__device__ __forceinline__ void mbar_wait_acq(uint32_t a, uint32_t ph) {
    asm volatile(
        "{\n\t.reg .pred P;\n\t"
        "WL%=:\n\t"
        "mbarrier.try_wait.parity.acquire.cta.shared::cta.b64 P, [%0], %1, 0x989680;\n\t"
        "@P bra.uni WD%=;\n\t"
        "bra.uni WL%=;\n\t"
        "WD%=:\n\t}"
        :: "r"(a), "r"(ph) : "memory");
}
__device__ __forceinline__ void ldsm_x4(uint32_t& r0, uint32_t& r1, uint32_t& r2,
                                        uint32_t& r3, uint32_t addr) {
    asm volatile("ldmatrix.sync.aligned.m8n8.x4.shared.b16 {%0,%1,%2,%3}, [%4];"
                 : "=r"(r0), "=r"(r1), "=r"(r2), "=r"(r3) : "r"(addr));
}
__device__ __forceinline__ void ldsm_x2t(uint32_t& r0, uint32_t& r1, uint32_t addr) {
    asm volatile("ldmatrix.sync.aligned.m8n8.x2.trans.shared.b16 {%0,%1}, [%2];"
                 : "=r"(r0), "=r"(r1) : "r"(addr));
}
__device__ __forceinline__ void mma16816(float& c0, float& c1, float& c2, float& c3,
                                         uint32_t a0, uint32_t a1, uint32_t a2, uint32_t a3,
                                         uint32_t b0, uint32_t b1) {
    asm volatile(
        "mma.sync.aligned.m16n8k16.row.col.f32.f16.f16.f32 "
        "{%0,%1,%2,%3}, {%4,%5,%6,%7}, {%8,%9}, {%0,%1,%2,%3};"
        : "+f"(c0), "+f"(c1), "+f"(c2), "+f"(c3)
        : "r"(a0), "r"(a1), "r"(a2), "r"(a3), "r"(b0), "r"(b1));
}

// All-CTA barrier. Valid because GRID16 CTAs are all co-resident (single wave).
// Monotone ticket counter -> correct across graph replays without reset.
__device__ __forceinline__ void grid_bar(int tid) {
    __syncthreads();
    if (tid == 0) {
        __threadfence();
        unsigned ticket = atomicAdd(&g_bar, 1u) + 1u;
        unsigned target = ((ticket + GRID16 - 1u) / GRID16) * GRID16;
        while (atomicAdd(&g_bar, 0u) < target) {}
        __threadfence();
    }
    __syncthreads();
}

// xT[m*8 + i] = x[i*M + m]
__global__ __launch_bounds__(256)
void transpose_kernel(const float* __restrict__ x, float* __restrict__ xT) {
    const int m = blockIdx.x * blockDim.x + threadIdx.x;
    if (m >= MDIM) return;
    float v[CIN];
#pragma unroll
    for (int i = 0; i < CIN; ++i) v[i] = x[(size_t)i * MDIM + m];
    float4* dst = reinterpret_cast<float4*>(xT + (size_t)m * CIN);
    dst[0] = make_float4(v[0], v[1], v[2], v[3]);
    dst[1] = make_float4(v[4], v[5], v[6], v[7]);
}

// ============ step 1: fp32 L, fp32 FFMA, emits L16 shadow + fp16 p1 ============
__global__ __launch_bounds__(NTHR32, 3)
void step32_kernel(const float* __restrict__ L,
                   const float* __restrict__ cur,
                   __half* __restrict__ nxt_h,
                   __half* __restrict__ L16out) {
    extern __shared__ __align__(128) unsigned char dsm[];
    const uint32_t smb = smem_u32(dsm);
    const int tid  = threadIdx.x;
    const int lane = tid & 31;
    const int w    = tid >> 5;
    const int m0   = blockIdx.x * RPB;

    if (tid == 0) {
#pragma unroll
        for (int s = 0; s < NS32; ++s) {
            mbar_init(smb + SM_FULL  + 8 * s, 32);
            mbar_init(smb + SM_EMPTY + 8 * s, NWC32);
        }
    }
    __syncthreads();

    if (w == NWC32) {
        const unsigned char* curb = reinterpret_cast<const unsigned char*>(cur);
        int eph = 1;
        for (int u = 0; u < NSTG; ++u) {
            const int slot = u & (NS32 - 1);
            mbar_wait_acq(smb + SM_EMPTY + 8 * slot, (uint32_t)eph);
            const uint32_t dst0 = smb + SM_RING + slot * STAGE_B32;
            const int jb = u * SCOLS;                 // forward
#pragma unroll
            for (int r = 0; r < RPB; ++r) {
                int mr = m0 + r; if (mr > MDIM - 1) mr = MDIM - 1;
                cp16(dst0 + r * (SCOLS * 4) + lane * 16,
                     L + (size_t)mr * MDIM + jb + lane * 4);
            }
#pragma unroll
            for (int q = 0; q < 8; ++q) {
                const uint32_t off = (uint32_t)(lane * 16 + q * 512);
                cp16(dst0 + STAGE_L32 + SWZ(off),
                     curb + (size_t)jb * 32 + off);
            }
            cp_commit();
            if (u >= 2) { cp_wait<2>(); mbar_arrive(smb + SM_FULL + 8 * ((u - 2) & (NS32 - 1))); }
            if (slot == NS32 - 1) eph ^= 1;
        }
        cp_wait<1>(); mbar_arrive(smb + SM_FULL + 8 * ((NSTG - 2) & (NS32 - 1)));
        cp_wait<0>(); mbar_arrive(smb + SM_FULL + 8 * ((NSTG - 1) & (NS32 - 1)));
        return;
    }

    const int r0 = w * RPW;
    unsigned long long acc[RPW][NPAIR];
#pragma unroll
    for (int r = 0; r < RPW; ++r)
#pragma unroll
        for (int p = 0; p < NPAIR; ++p) acc[r][p] = 0ull;

    int fph = 0;
    for (int u = 0; u < NSTG; ++u) {
        const int slot = u & (NS32 - 1);
        mbar_wait_acq(smb + SM_FULL + 8 * slot, (uint32_t)fph);

        const unsigned char* lb = dsm + SM_RING + slot * STAGE_B32;
        float4 a[RPW];
#pragma unroll
        for (int r = 0; r < RPW; ++r)
            a[r] = *reinterpret_cast<const float4*>(
                       lb + (r0 + r) * (SCOLS * 4) + lane * 16);

        // emit fp16 shadow of L
        const int jc = u * SCOLS + 4 * lane;
#pragma unroll
        for (int r = 0; r < RPW; ++r) {
            const int m = m0 + r0 + r;
            if (m < MDIM) {
                __half2 h01 = __floats2half2_rn(a[r].x, a[r].y);
                __half2 h23 = __floats2half2_rn(a[r].z, a[r].w);
                uint2 pkd;
                pkd.x = *reinterpret_cast<uint32_t*>(&h01);
                pkd.y = *reinterpret_cast<uint32_t*>(&h23);
                *reinterpret_cast<uint2*>(L16out + (size_t)m * MDIM + jc) = pkd;
            }
        }

        const unsigned char* pbp = lb + STAGE_L32;
#pragma unroll
        for (int jj = 0; jj < 4; ++jj) {
            const int jl = 4 * lane + jj;
            ulonglong2 q0 = *reinterpret_cast<const ulonglong2*>(pbp + SWZ(jl * 32));
            ulonglong2 q1 = *reinterpret_cast<const ulonglong2*>(pbp + SWZ(jl * 32 + 16));
#pragma unroll
            for (int r = 0; r < RPW; ++r) {
                float av = (jj == 0) ? a[r].x : (jj == 1) ? a[r].y
                         : (jj == 2) ? a[r].z : a[r].w;
                unsigned long long aa = pack2(av, av);
                fma2(acc[r][0], aa, q0.x);
                fma2(acc[r][1], aa, q0.y);
                fma2(acc[r][2], aa, q1.x);
                fma2(acc[r][3], aa, q1.y);
            }
        }

        if (lane == 0) mbar_arrive(smb + SM_EMPTY + 8 * slot);
        if (slot == NS32 - 1) fph ^= 1;
    }

#pragma unroll
    for (int r = 0; r < RPW; ++r) {
        const int m = m0 + r0 + r;
        float ov[CIN];
#pragma unroll
        for (int p = 0; p < NPAIR; ++p) {
            float v0, v1;
            unpack2(acc[r][p], v0, v1);
#pragma unroll
            for (int d = 16; d > 0; d >>= 1) {
                v0 += __shfl_down_sync(0xffffffffu, v0, d);
                v1 += __shfl_down_sync(0xffffffffu, v1, d);
            }
            ov[2 * p] = v0; ov[2 * p + 1] = v1;
        }
        if (lane == 0 && m < MDIM) {
            __half2 h0 = __floats2half2_rn(ov[0], ov[1]);
            __half2 h1 = __floats2half2_rn(ov[2], ov[3]);
            __half2 h2 = __floats2half2_rn(ov[4], ov[5]);
            __half2 h3 = __floats2half2_rn(ov[6], ov[7]);
            uint4 pkd;
            pkd.x = *reinterpret_cast<uint32_t*>(&h0);
            pkd.y = *reinterpret_cast<uint32_t*>(&h1);
            pkd.z = *reinterpret_cast<uint32_t*>(&h2);
            pkd.w = *reinterpret_cast<uint32_t*>(&h3);
            *reinterpret_cast<uint4*>(nxt_h + (size_t)m * CIN) = pkd;
        }
    }
}

// ============ steps 2-4 fused: persistent fp16 HMMA, grid barriers ============
__global__ __launch_bounds__(NTHR16, 3)
void step16_fused(const __half* __restrict__ Lh,
                  __half* __restrict__ panh) {
    extern __shared__ __align__(128) unsigned char dsm[];
    const uint32_t smb = smem_u32(dsm);
    const int tid  = threadIdx.x;
    const int lane = tid & 31;
    const int w    = tid >> 5;
    const int m0   = blockIdx.x * MROWS;
    const size_t PSZ = (size_t)MDIM * CIN;

    if (tid == 0) {
#pragma unroll
        for (int s = 0; s < NS16; ++s) {
            mbar_init(smb + SM_FULL  + 8 * s, 32);
            mbar_init(smb + SM_EMPTY + 8 * s, NWC16);
        }
    }
    __syncthreads();

    // Ring parity returns to initial after 96 stages (16 even wraps of NS16=6),
    // so each step reuses the same loop with fresh slot/phase counters.
    for (int step = 0; step < 3; ++step) {
        const int dir = 1 - (step & 1);               // steps 2,3,4 -> 1,0,1
        const __half* cur_h = panh + (size_t)step * PSZ;
        __half*       nxt_h = panh + (size_t)(step + 1) * PSZ;

        if (w == NWC16) {
            // ================= producer warp =================
            int slot = 0, eph = 1;
            for (int u = 0; u < NSTG; ++u) {
                const int t = dir ? (NSTG - 1 - u) : u;
                mbar_wait_acq(smb + SM_EMPTY + 8 * slot, (uint32_t)eph);
                const uint32_t dst0 = smb + SM_RING + slot * M_STAGE_B;
                const int jb = t * SCOLS;
                const int c = lane & 15;
#pragma unroll
                for (int rr = 0; rr < MROWS / 2; ++rr) {
                    const int r = 2 * rr + (lane >> 4);
                    const uint32_t phys = (uint32_t)(r * 256 + ((c & 8) << 4)
                                                     + (((c ^ r) & 7) << 4));
                    cp16(dst0 + phys,
                         Lh + (size_t)(m0 + r) * MDIM + jb + c * 8);
                }
#pragma unroll
                for (int q = 0; q < 4; ++q) {
                    const int j = q * 32 + lane;
                    cp16(dst0 + M_STAGE_L + j * 16,
                         cur_h + (size_t)(jb + j) * CIN);
                }
                cp_commit();
                if (u >= LAG) {
                    cp_wait<LAG>();
                    mbar_arrive(smb + SM_FULL + 8 * ((u - LAG) % NS16));
                }
                if (++slot == NS16) { slot = 0; eph ^= 1; }
            }
            cp_wait<3>(); mbar_arrive(smb + SM_FULL + 8 * ((NSTG - 4) % NS16));
            cp_wait<2>(); mbar_arrive(smb + SM_FULL + 8 * ((NSTG - 3) % NS16));
            cp_wait<1>(); mbar_arrive(smb + SM_FULL + 8 * ((NSTG - 2) % NS16));
            cp_wait<0>(); mbar_arrive(smb + SM_FULL + 8 * ((NSTG - 1) % NS16));
        } else {
            // ================= mma warps (16 rows each) =================
            float c0 = 0.f, c1 = 0.f, c2 = 0.f, c3 = 0.f;
            const uint32_t arow = (uint32_t)(w * 16 + (lane & 15));
            const uint32_t ca   = (uint32_t)(lane >> 4);

            int slot = 0, fph = 0;
            for (int u = 0; u < NSTG; ++u) {
                mbar_wait_acq(smb + SM_FULL + 8 * slot, (uint32_t)fph);

                const uint32_t lbase = smb + SM_RING + slot * M_STAGE_B;
                const uint32_t pbase = lbase + M_STAGE_L;
#pragma unroll
                for (int kb = 0; kb < 8; ++kb) {
                    const uint32_t c = 2 * kb + ca;
                    const uint32_t addrA = lbase + arow * 256 + ((c & 8) << 4)
                                           + (((c ^ arow) & 7) << 4);
                    uint32_t a0, a1, a2, a3;
                    ldsm_x4(a0, a1, a2, a3, addrA);
                    const uint32_t addrB = pbase + (kb * 16 + (lane & 15)) * 16;
                    uint32_t b0, b1;
                    ldsm_x2t(b0, b1, addrB);
                    mma16816(c0, c1, c2, c3, a0, a1, a2, a3, b0, b1);
                }

                if (lane == 0) mbar_arrive(smb + SM_EMPTY + 8 * slot);
                if (++slot == NS16) { slot = 0; fph ^= 1; }
            }

            // epilogue: C[16x8] -> fp16 panel rows
            const int row0 = m0 + w * 16 + (lane >> 2);
            const int n0   = (lane & 3) * 2;
            __half2 h0 = __floats2half2_rn(c0, c1);
            __half2 h1 = __floats2half2_rn(c2, c3);
            *reinterpret_cast<uint32_t*>(nxt_h + (size_t)row0 * CIN + n0) =
                *reinterpret_cast<uint32_t*>(&h0);
            *reinterpret_cast<uint32_t*>(nxt_h + (size_t)(row0 + 8) * CIN + n0) =
                *reinterpret_cast<uint32_t*>(&h1);
        }

        // publish panel step+1 to all CTAs before next step reads it
        if (step < 2) grid_bar(tid);
    }
}

// y[o][m] = bias[o] + sum_{i,k} theta[o][i][k] * P[k][m][i]
__global__ __launch_bounds__(256)
void mix_kernel(const float* __restrict__ x,
                const float* __restrict__ theta,
                const float* __restrict__ bias,
                float* __restrict__ out) {
    __shared__ float th[COUT * CIN * KTAP];
    __shared__ float bs[COUT];
    const int tid = threadIdx.x;
    for (int idx = tid; idx < COUT * CIN * KTAP; idx += blockDim.x)
        th[idx] = theta[idx];
    if (tid < COUT) bs[tid] = bias[tid];
    __syncthreads();

    const int m = blockIdx.x * blockDim.x + tid;
    if (m >= MDIM) return;

    float p[KTAP][CIN];
#pragma unroll
    for (int i = 0; i < CIN; ++i) p[0][i] = x[(size_t)i * MDIM + m];
#pragma unroll
    for (int k = 1; k < KTAP; ++k) {
        const uint2* src = reinterpret_cast<const uint2*>(
                               &g_panh[k - 1][(size_t)m * CIN]);
        uint2 lo = src[0], hi = src[1];
        float2 f0 = __half22float2(*reinterpret_cast<__half2*>(&lo.x));
        float2 f1 = __half22float2(*reinterpret_cast<__half2*>(&lo.y));
        float2 f2 = __half22float2(*reinterpret_cast<__half2*>(&hi.x));
        float2 f3 = __half22float2(*reinterpret_cast<__half2*>(&hi.y));
        p[k][0] = f0.x; p[k][1] = f0.y; p[k][2] = f1.x; p[k][3] = f1.y;
        p[k][4] = f2.x; p[k][5] = f2.y; p[k][6] = f3.x; p[k][7] = f3.y;
    }

#pragma unroll
    for (int o = 0; o < COUT; ++o) {
        float s = bs[o];
#pragma unroll
        for (int i = 0; i < CIN; ++i)
#pragma unroll
            for (int k = 0; k < KTAP; ++k)
                s += th[(o * CIN + i) * KTAP + k] * p[k][i];
        out[(size_t)o * MDIM + m] = s;
    }
}

extern "C" void kernel_launch(void* const* d_in, const int* in_sizes, int n_in,
                              void* d_out, int out_size) {
    const float* L     = (const float*)d_in[0];
    const float* x     = (const float*)d_in[1];
    const float* theta = (const float*)d_in[2];
    const float* bias  = (const float*)d_in[3];
    float* out = (float*)d_out;

    cudaFuncSetAttribute(step32_kernel,
                         cudaFuncAttributeMaxDynamicSharedMemorySize, SMEM32);
    cudaFuncSetAttribute(step16_fused,
                         cudaFuncAttributeMaxDynamicSharedMemorySize, SMEM16);

    __half* panh = nullptr;
    cudaGetSymbolAddress((void**)&panh, g_panh);
    float* xT = nullptr;
    cudaGetSymbolAddress((void**)&xT, g_xT);
    __half* L16 = nullptr;
    cudaGetSymbolAddress((void**)&L16, g_L16);

    const size_t PSZ = (size_t)MDIM * CIN;

    transpose_kernel<<<(MDIM + 255) / 256, 256>>>(x, xT);
    // Step 1: fp32 L (forward), emits fp16 shadow + fp16 p1.
    step32_kernel<<<GRID32, NTHR32, SMEM32>>>(L, xT, panh + 0 * PSZ, L16);
    // Steps 2-4 fused: persistent HMMA kernel, serpentine, grid barriers.
    step16_fused<<<GRID16, NTHR16, SMEM16>>>(L16, panh);

    mix_kernel<<<(MDIM + 255) / 256, 256>>>(x, theta, bias, out);
}

// round 17
// speedup vs baseline: 1.3596x; 1.0036x over previous
#include <cuda_runtime.h>
#include <cuda_fp16.h>
#include <cstdint>

#define MDIM 12288
#define CIN 8
#define NPAIR 4
#define COUT 16
#define KTAP 5

// ---------- step32 (step 1) geometry: R11 winner ----------
#define RPW 7
#define NWC32 4
#define RPB (RPW * NWC32)        // 28
#define NCTHR (NWC32 * 32)
#define NTHR32 (NCTHR + 32)      // 160
#define GRID32 439

#define SCOLS 128
#define NS32 4
#define NSTG (MDIM / SCOLS)      // 96
#define STAGE_L32 (RPB * SCOLS * 4)      // 14336
#define STAGE_P32 (SCOLS * CIN * 4)      // 4096
#define STAGE_B32 (STAGE_L32 + STAGE_P32)
#define SMEM32 (128 + NS32 * STAGE_B32)  // 73856

// ---------- step16 MMA geometry ----------
#define MROWS 32                 // rows per CTA (2 mma warps x 16)
#define GRID16 (MDIM / MROWS)    // 384  (single wave -> co-resident)
#define NWC16 2
#define NTHR16 ((NWC16 + 1) * 32)    // 96
#define NS16 6
#define LAG 4
#define M_STAGE_L (MROWS * SCOLS * 2)    // 8192
#define M_STAGE_P (SCOLS * CIN * 2)      // 2048
#define M_STAGE_B (M_STAGE_L + M_STAGE_P)  // 10240
#define SM_TH   (128 + NS16 * M_STAGE_B)   // 61568: theta/bias staging
#define TH_FLOATS (COUT * CIN * KTAP + COUT)   // 656
#define SMEM16 (SM_TH + TH_FLOATS * 4)     // 64192 -> still 3 CTAs/SM

#define SM_FULL  0
#define SM_EMPTY 64
#define SM_RING  128

#define SWZ(b) ((b) ^ (((b) >> 3) & 0x70))

__device__ __align__(16) __half g_panh[KTAP - 1][MDIM * CIN];  // p1..p4 fp16 [M][8]
__device__ __align__(16) float  g_xT[MDIM * CIN];
__device__ __align__(16) __half g_L16[(size_t)MDIM * MDIM];
__device__ unsigned g_bar = 0;   // monotone grid-barrier ticket counter

// ---------- helpers ----------
__device__ __forceinline__ uint32_t smem_u32(const void* p) {
    uint32_t a;
    asm("{ .reg .u64 t; cvta.to.shared.u64 t, %1; cvt.u32.u64 %0, t; }" : "=r"(a) : "l"(p));
    return a;
}
__device__ __forceinline__ unsigned long long pack2(float lo, float hi) {
    unsigned long long r;
    asm("mov.b64 %0, {%1, %2};" : "=l"(r) : "f"(lo), "f"(hi));
    return r;
}
__device__ __forceinline__ void unpack2(unsigned long long v, float& lo, float& hi) {
    asm("mov.b64 {%0, %1}, %2;" : "=f"(lo), "=f"(hi) : "l"(v));
}
__device__ __forceinline__ void fma2(unsigned long long& acc,
                                     unsigned long long a, unsigned long long b) {
    asm("fma.rn.f32x2 %0, %1, %2, %0;" : "+l"(acc) : "l"(a), "l"(b));
}
__device__ __forceinline__ void cp16(uint32_t dst, const void* src) {
    asm volatile("cp.async.cg.shared.global [%0], [%1], 16;" :: "r"(dst), "l"(src) : "memory");
}
__device__ __forceinline__ void cp_commit() {
    asm volatile("cp.async.commit_group;" ::: "memory");
}
template <int N>
__device__ __forceinline__ void cp_wait() {
    asm volatile("cp.async.wait_group %0;" :: "n"(N) : "memory");
}
__device__ __forceinline__ void mbar_init(uint32_t a, uint32_t cnt) {
    asm volatile("mbarrier.init.shared.b64 [%0], %1;" :: "r"(a), "r"(cnt) : "memory");
}
__device__ __forceinline__ void mbar_arrive(uint32_t a) {
    asm volatile("mbarrier.arrive.release.cta.shared::cta.b64 _, [%0];" :: "r"(a) : "memory");
}
__device__ __forceinline__ void mbar_wait_acq(uint32_t a, uint32_t ph) {
    asm volatile(
        "{\n\t.reg .pred P;\n\t"
        "WL%=:\n\t"
        "mbarrier.try_wait.parity.acquire.cta.shared::cta.b64 P, [%0], %1, 0x989680;\n\t"
        "@P bra.uni WD%=;\n\t"
        "bra.uni WL%=;\n\t"
        "WD%=:\n\t}"
        :: "r"(a), "r"(ph) : "memory");
}
__device__ __forceinline__ void ldsm_x4(uint32_t& r0, uint32_t& r1, uint32_t& r2,
                                        uint32_t& r3, uint32_t addr) {
    asm volatile("ldmatrix.sync.aligned.m8n8.x4.shared.b16 {%0,%1,%2,%3}, [%4];"
                 : "=r"(r0), "=r"(r1), "=r"(r2), "=r"(r3) : "r"(addr));
}
__device__ __forceinline__ void ldsm_x2t(uint32_t& r0, uint32_t& r1, uint32_t addr) {
    asm volatile("ldmatrix.sync.aligned.m8n8.x2.trans.shared.b16 {%0,%1}, [%2];"
                 : "=r"(r0), "=r"(r1) : "r"(addr));
}
__device__ __forceinline__ void mma16816(float& c0, float& c1, float& c2, float& c3,
                                         uint32_t a0, uint32_t a1, uint32_t a2, uint32_t a3,
                                         uint32_t b0, uint32_t b1) {
    asm volatile(
        "mma.sync.aligned.m16n8k16.row.col.f32.f16.f16.f32 "
        "{%0,%1,%2,%3}, {%4,%5,%6,%7}, {%8,%9}, {%0,%1,%2,%3};"
        : "+f"(c0), "+f"(c1), "+f"(c2), "+f"(c3)
        : "r"(a0), "r"(a1), "r"(a2), "r"(a3), "r"(b0), "r"(b1));
}

// All-CTA barrier (all GRID16 CTAs co-resident; monotone ticket -> replay-safe).
__device__ __forceinline__ void grid_bar(int tid) {
    __syncthreads();
    if (tid == 0) {
        __threadfence();
        unsigned ticket = atomicAdd(&g_bar, 1u) + 1u;
        unsigned target = ((ticket + GRID16 - 1u) / GRID16) * GRID16;
        while (atomicAdd(&g_bar, 0u) < target) {}
        __threadfence();
    }
    __syncthreads();
}

// xT[m*8 + i] = x[i*M + m]
__global__ __launch_bounds__(256)
void transpose_kernel(const float* __restrict__ x, float* __restrict__ xT) {
    const int m = blockIdx.x * blockDim.x + threadIdx.x;
    if (m >= MDIM) return;
    float v[CIN];
#pragma unroll
    for (int i = 0; i < CIN; ++i) v[i] = x[(size_t)i * MDIM + m];
    float4* dst = reinterpret_cast<float4*>(xT + (size_t)m * CIN);
    dst[0] = make_float4(v[0], v[1], v[2], v[3]);
    dst[1] = make_float4(v[4], v[5], v[6], v[7]);
}

// ============ step 1: fp32 L, fp32 FFMA, emits L16 shadow + fp16 p1 ============
__global__ __launch_bounds__(NTHR32, 3)
void step32_kernel(const float* __restrict__ L,
                   const float* __restrict__ cur,
                   __half* __restrict__ nxt_h,
                   __half* __restrict__ L16out) {
    extern __shared__ __align__(128) unsigned char dsm[];
    const uint32_t smb = smem_u32(dsm);
    const int tid  = threadIdx.x;
    const int lane = tid & 31;
    const int w    = tid >> 5;
    const int m0   = blockIdx.x * RPB;

    if (tid == 0) {
#pragma unroll
        for (int s = 0; s < NS32; ++s) {
            mbar_init(smb + SM_FULL  + 8 * s, 32);
            mbar_init(smb + SM_EMPTY + 8 * s, NWC32);
        }
    }
    __syncthreads();

    if (w == NWC32) {
        const unsigned char* curb = reinterpret_cast<const unsigned char*>(cur);
        int eph = 1;
        for (int u = 0; u < NSTG; ++u) {
            const int slot = u & (NS32 - 1);
            mbar_wait_acq(smb + SM_EMPTY + 8 * slot, (uint32_t)eph);
            const uint32_t dst0 = smb + SM_RING + slot * STAGE_B32;
            const int jb = u * SCOLS;                 // forward
#pragma unroll
            for (int r = 0; r < RPB; ++r) {
                int mr = m0 + r; if (mr > MDIM - 1) mr = MDIM - 1;
                cp16(dst0 + r * (SCOLS * 4) + lane * 16,
                     L + (size_t)mr * MDIM + jb + lane * 4);
            }
#pragma unroll
            for (int q = 0; q < 8; ++q) {
                const uint32_t off = (uint32_t)(lane * 16 + q * 512);
                cp16(dst0 + STAGE_L32 + SWZ(off),
                     curb + (size_t)jb * 32 + off);
            }
            cp_commit();
            if (u >= 2) { cp_wait<2>(); mbar_arrive(smb + SM_FULL + 8 * ((u - 2) & (NS32 - 1))); }
            if (slot == NS32 - 1) eph ^= 1;
        }
        cp_wait<1>(); mbar_arrive(smb + SM_FULL + 8 * ((NSTG - 2) & (NS32 - 1)));
        cp_wait<0>(); mbar_arrive(smb + SM_FULL + 8 * ((NSTG - 1) & (NS32 - 1)));
        return;
    }

    const int r0 = w * RPW;
    unsigned long long acc[RPW][NPAIR];
#pragma unroll
    for (int r = 0; r < RPW; ++r)
#pragma unroll
        for (int p = 0; p < NPAIR; ++p) acc[r][p] = 0ull;

    int fph = 0;
    for (int u = 0; u < NSTG; ++u) {
        const int slot = u & (NS32 - 1);
        mbar_wait_acq(smb + SM_FULL + 8 * slot, (uint32_t)fph);

        const unsigned char* lb = dsm + SM_RING + slot * STAGE_B32;
        float4 a[RPW];
#pragma unroll
        for (int r = 0; r < RPW; ++r)
            a[r] = *reinterpret_cast<const float4*>(
                       lb + (r0 + r) * (SCOLS * 4) + lane * 16);

        // emit fp16 shadow of L
        const int jc = u * SCOLS + 4 * lane;
#pragma unroll
        for (int r = 0; r < RPW; ++r) {
            const int m = m0 + r0 + r;
            if (m < MDIM) {
                __half2 h01 = __floats2half2_rn(a[r].x, a[r].y);
                __half2 h23 = __floats2half2_rn(a[r].z, a[r].w);
                uint2 pkd;
                pkd.x = *reinterpret_cast<uint32_t*>(&h01);
                pkd.y = *reinterpret_cast<uint32_t*>(&h23);
                *reinterpret_cast<uint2*>(L16out + (size_t)m * MDIM + jc) = pkd;
            }
        }

        const unsigned char* pbp = lb + STAGE_L32;
#pragma unroll
        for (int jj = 0; jj < 4; ++jj) {
            const int jl = 4 * lane + jj;
            ulonglong2 q0 = *reinterpret_cast<const ulonglong2*>(pbp + SWZ(jl * 32));
            ulonglong2 q1 = *reinterpret_cast<const ulonglong2*>(pbp + SWZ(jl * 32 + 16));
#pragma unroll
            for (int r = 0; r < RPW; ++r) {
                float av = (jj == 0) ? a[r].x : (jj == 1) ? a[r].y
                         : (jj == 2) ? a[r].z : a[r].w;
                unsigned long long aa = pack2(av, av);
                fma2(acc[r][0], aa, q0.x);
                fma2(acc[r][1], aa, q0.y);
                fma2(acc[r][2], aa, q1.x);
                fma2(acc[r][3], aa, q1.y);
            }
        }

        if (lane == 0) mbar_arrive(smb + SM_EMPTY + 8 * slot);
        if (slot == NS32 - 1) fph ^= 1;
    }

#pragma unroll
    for (int r = 0; r < RPW; ++r) {
        const int m = m0 + r0 + r;
        float ov[CIN];
#pragma unroll
        for (int p = 0; p < NPAIR; ++p) {
            float v0, v1;
            unpack2(acc[r][p], v0, v1);
#pragma unroll
            for (int d = 16; d > 0; d >>= 1) {
                v0 += __shfl_down_sync(0xffffffffu, v0, d);
                v1 += __shfl_down_sync(0xffffffffu, v1, d);
            }
            ov[2 * p] = v0; ov[2 * p + 1] = v1;
        }
        if (lane == 0 && m < MDIM) {
            __half2 h0 = __floats2half2_rn(ov[0], ov[1]);
            __half2 h1 = __floats2half2_rn(ov[2], ov[3]);
            __half2 h2 = __floats2half2_rn(ov[4], ov[5]);
            __half2 h3 = __floats2half2_rn(ov[6], ov[7]);
            uint4 pkd;
            pkd.x = *reinterpret_cast<uint32_t*>(&h0);
            pkd.y = *reinterpret_cast<uint32_t*>(&h1);
            pkd.z = *reinterpret_cast<uint32_t*>(&h2);
            pkd.w = *reinterpret_cast<uint32_t*>(&h3);
            *reinterpret_cast<uint4*>(nxt_h + (size_t)m * CIN) = pkd;
        }
    }
}

// ==== steps 2-4 fused + mix epilogue: persistent HMMA, grid barriers ====
__global__ __launch_bounds__(NTHR16, 3)
void step16_fused(const __half* __restrict__ Lh,
                  __half* __restrict__ panh,
                  const float* __restrict__ xT,
                  const float* __restrict__ theta,
                  const float* __restrict__ bias,
                  float* __restrict__ out) {
    extern __shared__ __align__(128) unsigned char dsm[];
    const uint32_t smb = smem_u32(dsm);
    const int tid  = threadIdx.x;
    const int lane = tid & 31;
    const int w    = tid >> 5;
    const int m0   = blockIdx.x * MROWS;
    const size_t PSZ = (size_t)MDIM * CIN;

    // stage theta+bias into smem (reused at the tail)
    float* thsm = reinterpret_cast<float*>(dsm + SM_TH);
    for (int idx = tid; idx < COUT * CIN * KTAP; idx += NTHR16)
        thsm[idx] = theta[idx];
    if (tid < COUT) thsm[COUT * CIN * KTAP + tid] = bias[tid];

    if (tid == 0) {
#pragma unroll
        for (int s = 0; s < NS16; ++s) {
            mbar_init(smb + SM_FULL  + 8 * s, 32);
            mbar_init(smb + SM_EMPTY + 8 * s, NWC16);
        }
    }
    __syncthreads();

    // Ring parity returns to initial after 96 stages (16 wraps of NS16=6).
    for (int step = 0; step < 3; ++step) {
        const int dir = 1 - (step & 1);               // steps 2,3,4 -> 1,0,1
        const __half* cur_h = panh + (size_t)step * PSZ;
        __half*       nxt_h = panh + (size_t)(step + 1) * PSZ;

        if (w == NWC16) {
            // ================= producer warp =================
            int slot = 0, eph = 1;
            for (int u = 0; u < NSTG; ++u) {
                const int t = dir ? (NSTG - 1 - u) : u;
                mbar_wait_acq(smb + SM_EMPTY + 8 * slot, (uint32_t)eph);
                const uint32_t dst0 = smb + SM_RING + slot * M_STAGE_B;
                const int jb = t * SCOLS;
                const int c = lane & 15;
#pragma unroll
                for (int rr = 0; rr < MROWS / 2; ++rr) {
                    const int r = 2 * rr + (lane >> 4);
                    const uint32_t phys = (uint32_t)(r * 256 + ((c & 8) << 4)
                                                     + (((c ^ r) & 7) << 4));
                    cp16(dst0 + phys,
                         Lh + (size_t)(m0 + r) * MDIM + jb + c * 8);
                }
#pragma unroll
                for (int q = 0; q < 4; ++q) {
                    const int j = q * 32 + lane;
                    cp16(dst0 + M_STAGE_L + j * 16,
                         cur_h + (size_t)(jb + j) * CIN);
                }
                cp_commit();
                if (u >= LAG) {
                    cp_wait<LAG>();
                    mbar_arrive(smb + SM_FULL + 8 * ((u - LAG) % NS16));
                }
                if (++slot == NS16) { slot = 0; eph ^= 1; }
            }
            cp_wait<3>(); mbar_arrive(smb + SM_FULL + 8 * ((NSTG - 4) % NS16));
            cp_wait<2>(); mbar_arrive(smb + SM_FULL + 8 * ((NSTG - 3) % NS16));
            cp_wait<1>(); mbar_arrive(smb + SM_FULL + 8 * ((NSTG - 2) % NS16));
            cp_wait<0>(); mbar_arrive(smb + SM_FULL + 8 * ((NSTG - 1) % NS16));
        } else {
            // ================= mma warps (16 rows each) =================
            float c0 = 0.f, c1 = 0.f, c2 = 0.f, c3 = 0.f;
            const uint32_t arow = (uint32_t)(w * 16 + (lane & 15));
            const uint32_t ca   = (uint32_t)(lane >> 4);

            int slot = 0, fph = 0;
            for (int u = 0; u < NSTG; ++u) {
                mbar_wait_acq(smb + SM_FULL + 8 * slot, (uint32_t)fph);

                const uint32_t lbase = smb + SM_RING + slot * M_STAGE_B;
                const uint32_t pbase = lbase + M_STAGE_L;
#pragma unroll
                for (int kb = 0; kb < 8; ++kb) {
                    const uint32_t c = 2 * kb + ca;
                    const uint32_t addrA = lbase + arow * 256 + ((c & 8) << 4)
                                           + (((c ^ arow) & 7) << 4);
                    uint32_t a0, a1, a2, a3;
                    ldsm_x4(a0, a1, a2, a3, addrA);
                    const uint32_t addrB = pbase + (kb * 16 + (lane & 15)) * 16;
                    uint32_t b0, b1;
                    ldsm_x2t(b0, b1, addrB);
                    mma16816(c0, c1, c2, c3, a0, a1, a2, a3, b0, b1);
                }

                if (lane == 0) mbar_arrive(smb + SM_EMPTY + 8 * slot);
                if (++slot == NS16) { slot = 0; fph ^= 1; }
            }

            // epilogue: C[16x8] -> fp16 panel rows
            const int row0 = m0 + w * 16 + (lane >> 2);
            const int n0   = (lane & 3) * 2;
            __half2 h0 = __floats2half2_rn(c0, c1);
            __half2 h1 = __floats2half2_rn(c2, c3);
            *reinterpret_cast<uint32_t*>(nxt_h + (size_t)row0 * CIN + n0) =
                *reinterpret_cast<uint32_t*>(&h0);
            *reinterpret_cast<uint32_t*>(nxt_h + (size_t)(row0 + 8) * CIN + n0) =
                *reinterpret_cast<uint32_t*>(&h1);
        }

        // publish panel step+1 to all CTAs before next step reads it
        if (step < 2) grid_bar(tid);
    }

    // ================= mix tail: y = bias + theta * panels =================
    // p4 for this CTA's rows was stored by its own warps; __syncthreads makes
    // those global stores visible block-wide. p1..p3 were grid-barriered.
    __syncthreads();
    {
        const float* bssm = thsm + COUT * CIN * KTAP;
        const int m = m0 + lane;            // each lane owns one row

        float p[KTAP][CIN];
        {
            const float4* s0 = reinterpret_cast<const float4*>(xT + (size_t)m * CIN);
            float4 lo = s0[0], hi = s0[1];
            p[0][0] = lo.x; p[0][1] = lo.y; p[0][2] = lo.z; p[0][3] = lo.w;
            p[0][4] = hi.x; p[0][5] = hi.y; p[0][6] = hi.z; p[0][7] = hi.w;
        }
#pragma unroll
        for (int k = 1; k < KTAP; ++k) {
            const uint2* src = reinterpret_cast<const uint2*>(
                                   panh + (size_t)(k - 1) * PSZ + (size_t)m * CIN);
            uint2 lo = src[0], hi = src[1];
            float2 f0 = __half22float2(*reinterpret_cast<__half2*>(&lo.x));
            float2 f1 = __half22float2(*reinterpret_cast<__half2*>(&lo.y));
            float2 f2 = __half22float2(*reinterpret_cast<__half2*>(&hi.x));
            float2 f3 = __half22float2(*reinterpret_cast<__half2*>(&hi.y));
            p[k][0] = f0.x; p[k][1] = f0.y; p[k][2] = f1.x; p[k][3] = f1.y;
            p[k][4] = f2.x; p[k][5] = f2.y; p[k][6] = f3.x; p[k][7] = f3.y;
        }

        // warp w handles outputs o = w, w+3, ... -> coalesced 128B stores
        for (int o = w; o < COUT; o += 3) {
            float s = bssm[o];
#pragma unroll
            for (int i = 0; i < CIN; ++i) {
                const float* th = thsm + (o * CIN + i) * KTAP;
#pragma unroll
                for (int k = 0; k < KTAP; ++k)
                    s += th[k] * p[k][i];
            }
            out[(size_t)o * MDIM + m] = s;
        }
    }
}

extern "C" void kernel_launch(void* const* d_in, const int* in_sizes, int n_in,
                              void* d_out, int out_size) {
    const float* L     = (const float*)d_in[0];
    const float* x     = (const float*)d_in[1];
    const float* theta = (const float*)d_in[2];
    const float* bias  = (const float*)d_in[3];
    float* out = (float*)d_out;

    cudaFuncSetAttribute(step32_kernel,
                         cudaFuncAttributeMaxDynamicSharedMemorySize, SMEM32);
    cudaFuncSetAttribute(step16_fused,
                         cudaFuncAttributeMaxDynamicSharedMemorySize, SMEM16);

    __half* panh = nullptr;
    cudaGetSymbolAddress((void**)&panh, g_panh);
    float* xT = nullptr;
    cudaGetSymbolAddress((void**)&xT, g_xT);
    __half* L16 = nullptr;
    cudaGetSymbolAddress((void**)&L16, g_L16);

    const size_t PSZ = (size_t)MDIM * CIN;

    transpose_kernel<<<(MDIM + 255) / 256, 256>>>(x, xT);
    // Step 1: fp32 L (forward), emits fp16 shadow + fp16 p1.
    step32_kernel<<<GRID32, NTHR32, SMEM32>>>(L, xT, panh + 0 * PSZ, L16);
    // Steps 2-4 + mix, fused: persistent HMMA kernel, serpentine, grid barriers.
    step16_fused<<<GRID16, NTHR16, SMEM16>>>(L16, panh, xT, theta, bias, out);
}